// round 3
// baseline (speedup 1.0000x reference)
#include <cuda_runtime.h>
#include <math.h>

// Problem constants (fixed shapes)
#define BB 32768
#define DD 1024
#define KK 512
#define INV_T 10.0f

// ---------------- scratch (static device globals; no runtime alloc) ---------
__device__ float g_bufA[16777216];   // Zs, then scores_t -> E (in place)
__device__ float g_bufB[16777216];   // scores_s
__device__ float g_bufC[16777216];   // Zt
__device__ float g_Cn[KK * KK];
__device__ float g_invn[BB];
__device__ float g_beta[BB];
__device__ float g_lse[BB];
__device__ float g_R[KK];
__device__ float g_alpha[KK];
__device__ float g_M;
__device__ float g_S;
__device__ float g_loss;

// ---------------- helpers ----------------------------------------------------
__device__ __forceinline__ void atomicMaxF(float* addr, float val) {
    int* a = (int*)addr;
    int old = *a;
    while (__int_as_float(old) < val) {
        int assumed = old;
        old = atomicCAS(a, assumed, __float_as_int(val));
        if (old == assumed) break;
    }
}

// ---------------- init --------------------------------------------------------
__global__ void k_init() {
    int t = threadIdx.x;            // 512 threads
    g_R[t] = 0.0f;
    if (t == 0) {
        g_M = __int_as_float(0xff800000);  // -inf
        g_loss = 0.0f;
    }
}

// ---------------- Cn = row-l2-normalize(W_proto) [512,512] --------------------
// Writes g_Cn directly (device symbol).
__global__ void k_proto(const float* __restrict__ W) {
    int row = blockIdx.x;          // 512 blocks
    int t = threadIdx.x;           // 128 threads
    const float4* wr = (const float4*)(W + (size_t)row * KK);
    float4 v = wr[t];
    float s = v.x * v.x + v.y * v.y + v.z * v.z + v.w * v.w;
    __shared__ float sm[128];
    sm[t] = s;
    __syncthreads();
    for (int o = 64; o > 0; o >>= 1) {
        if (t < o) sm[t] += sm[t + o];
        __syncthreads();
    }
    float inv = 1.0f / sqrtf(sm[0]);
    float4 o4 = make_float4(v.x * inv, v.y * inv, v.z * inv, v.w * inv);
    ((float4*)(g_Cn + (size_t)row * KK))[t] = o4;
}

// ---------------- SGEMM (NT): C[m,n] = scale[m] * sum_k A[m,k]*Bm[n,k] --------
// 128x128 tile, 256 threads, 8x8 per thread, k-tile 8, register prefetch.
// All pointers are REAL device pointers (inputs or cudaGetSymbolAddress).
__global__ void k_sgemm(const float* __restrict__ A, const float* __restrict__ Bm,
                        float* __restrict__ C, int N, int Kd,
                        const float* __restrict__ rowScale, int doMax) {
    __shared__ float As[8][132];
    __shared__ float Bs[8][132];
    __shared__ float wm[8];

    int tid = threadIdx.x;
    int m0 = blockIdx.y * 128;
    int n0 = blockIdx.x * 128;

    int lr = tid >> 1;             // 0..127
    int lc = (tid & 1) * 4;        // 0 or 4
    const float* Ap = A + (size_t)(m0 + lr) * Kd + lc;
    const float* Bp = Bm + (size_t)(n0 + lr) * Kd + lc;

    int tx = tid & 15;
    int ty = tid >> 4;

    float acc[8][8];
#pragma unroll
    for (int i = 0; i < 8; i++)
#pragma unroll
        for (int j = 0; j < 8; j++) acc[i][j] = 0.0f;

    float4 ar = *(const float4*)Ap;
    float4 br = *(const float4*)Bp;

    int ktn = Kd >> 3;
    for (int kt = 0; kt < ktn; kt++) {
        As[lc + 0][lr] = ar.x; As[lc + 1][lr] = ar.y;
        As[lc + 2][lr] = ar.z; As[lc + 3][lr] = ar.w;
        Bs[lc + 0][lr] = br.x; Bs[lc + 1][lr] = br.y;
        Bs[lc + 2][lr] = br.z; Bs[lc + 3][lr] = br.w;
        __syncthreads();
        if (kt + 1 < ktn) {
            ar = *(const float4*)(Ap + (size_t)(kt + 1) * 8);
            br = *(const float4*)(Bp + (size_t)(kt + 1) * 8);
        }
#pragma unroll
        for (int kk = 0; kk < 8; kk++) {
            float4 a0 = *(const float4*)&As[kk][ty * 4];
            float4 a1 = *(const float4*)&As[kk][64 + ty * 4];
            float4 b0 = *(const float4*)&Bs[kk][tx * 4];
            float4 b1 = *(const float4*)&Bs[kk][64 + tx * 4];
            float av[8] = {a0.x, a0.y, a0.z, a0.w, a1.x, a1.y, a1.z, a1.w};
            float bv[8] = {b0.x, b0.y, b0.z, b0.w, b1.x, b1.y, b1.z, b1.w};
#pragma unroll
            for (int i = 0; i < 8; i++)
#pragma unroll
                for (int j = 0; j < 8; j++)
                    acc[i][j] = fmaf(av[i], bv[j], acc[i][j]);
        }
        __syncthreads();
    }

    float lmax = __int_as_float(0xff800000);
#pragma unroll
    for (int i = 0; i < 8; i++) {
        int m = m0 + ((i < 4) ? (ty * 4 + i) : (64 + ty * 4 + i - 4));
        float rs = rowScale ? rowScale[m] : 1.0f;
        float4 o0, o1;
        o0.x = acc[i][0] * rs; o0.y = acc[i][1] * rs;
        o0.z = acc[i][2] * rs; o0.w = acc[i][3] * rs;
        o1.x = acc[i][4] * rs; o1.y = acc[i][5] * rs;
        o1.z = acc[i][6] * rs; o1.w = acc[i][7] * rs;
        if (doMax) {
            lmax = fmaxf(lmax, fmaxf(fmaxf(o0.x, o0.y), fmaxf(o0.z, o0.w)));
            lmax = fmaxf(lmax, fmaxf(fmaxf(o1.x, o1.y), fmaxf(o1.z, o1.w)));
        }
        *(float4*)(C + (size_t)m * N + n0 + tx * 4) = o0;
        *(float4*)(C + (size_t)m * N + n0 + 64 + tx * 4) = o1;
    }

    if (doMax) {
#pragma unroll
        for (int o = 16; o > 0; o >>= 1)
            lmax = fmaxf(lmax, __shfl_xor_sync(0xffffffffu, lmax, o));
        if ((tid & 31) == 0) wm[tid >> 5] = lmax;
        __syncthreads();
        if (tid == 0) {
            float m2 = wm[0];
#pragma unroll
            for (int i = 1; i < 8; i++) m2 = fmaxf(m2, wm[i]);
            atomicMaxF(&g_M, m2);
        }
    }
}

// ---------------- inv row norm: g_invn[b] = 1/||Z[b,:]|| ----------------------
__global__ void k_rowinv(const float* __restrict__ Z) {
    int warp = threadIdx.x >> 5;
    int lane = threadIdx.x & 31;
    int row = blockIdx.x * 8 + warp;
    const float4* p = (const float4*)(Z + (size_t)row * KK);
    float s = 0.0f;
#pragma unroll
    for (int i = 0; i < 4; i++) {
        float4 v = p[i * 32 + lane];
        s += v.x * v.x + v.y * v.y + v.z * v.z + v.w * v.w;
    }
#pragma unroll
    for (int o = 16; o > 0; o >>= 1) s += __shfl_xor_sync(0xffffffffu, s, o);
    if (lane == 0) g_invn[row] = 1.0f / sqrtf(s);
}

// ---------------- g_lse[b] of g_bufB (scores_s) / T ---------------------------
__global__ void k_lse() {
    int warp = threadIdx.x >> 5;
    int lane = threadIdx.x & 31;
    int row = blockIdx.x * 8 + warp;
    const float4* p = (const float4*)(g_bufB + (size_t)row * KK);
    float4 v[4];
    float mx = __int_as_float(0xff800000);
#pragma unroll
    for (int i = 0; i < 4; i++) {
        v[i] = p[i * 32 + lane];
        v[i].x *= INV_T; v[i].y *= INV_T; v[i].z *= INV_T; v[i].w *= INV_T;
        mx = fmaxf(mx, fmaxf(fmaxf(v[i].x, v[i].y), fmaxf(v[i].z, v[i].w)));
    }
#pragma unroll
    for (int o = 16; o > 0; o >>= 1) mx = fmaxf(mx, __shfl_xor_sync(0xffffffffu, mx, o));
    float s = 0.0f;
#pragma unroll
    for (int i = 0; i < 4; i++)
        s += expf(v[i].x - mx) + expf(v[i].y - mx) + expf(v[i].z - mx) + expf(v[i].w - mx);
#pragma unroll
    for (int o = 16; o > 0; o >>= 1) s += __shfl_xor_sync(0xffffffffu, s, o);
    if (lane == 0) g_lse[row] = mx + logf(s);
}

// ---------------- E = exp((scores_t - M)/T) in g_bufA, col-accumulate R_k ------
__global__ void k_expcol() {
    int t = threadIdx.x;           // 256
    int base = blockIdx.x * 128;   // 256 blocks
    float Mv = g_M;
    float a0 = 0.0f, a1 = 0.0f;
    for (int r = 0; r < 128; r++) {
        size_t idx = (size_t)(base + r) * KK + t;
        float e0 = expf((g_bufA[idx] - Mv) * INV_T);
        g_bufA[idx] = e0; a0 += e0;
        float e1 = expf((g_bufA[idx + 256] - Mv) * INV_T);
        g_bufA[idx + 256] = e1; a1 += e1;
    }
    atomicAdd(&g_R[t], a0);
    atomicAdd(&g_R[t + 256], a1);
}

// ---------------- alpha_k = S / (K * R_k), reset R ----------------------------
__global__ void k_alpha(int first) {
    int t = threadIdx.x;           // 512
    float Rk = g_R[t];
    __shared__ float sm[512];
    float S;
    if (first) {
        sm[t] = Rk;
        __syncthreads();
        for (int o = 256; o > 0; o >>= 1) {
            if (t < o) sm[t] += sm[t + o];
            __syncthreads();
        }
        S = sm[0];
        if (t == 0) g_S = S;
    } else {
        S = g_S;
    }
    g_alpha[t] = S / (512.0f * Rk);
    g_R[t] = 0.0f;
}

// ---------------- beta_b = S / (B * sum_k E[b,k]*alpha_k) ---------------------
__global__ void k_rowpass() {
    int warp = threadIdx.x >> 5;
    int lane = threadIdx.x & 31;
    int row = blockIdx.x * 8 + warp;
    const float4* p = (const float4*)(g_bufA + (size_t)row * KK);
    const float4* a = (const float4*)g_alpha;
    float c = 0.0f;
#pragma unroll
    for (int i = 0; i < 4; i++) {
        float4 e = p[i * 32 + lane];
        float4 al = a[i * 32 + lane];
        c += e.x * al.x + e.y * al.y + e.z * al.z + e.w * al.w;
    }
#pragma unroll
    for (int o = 16; o > 0; o >>= 1) c += __shfl_xor_sync(0xffffffffu, c, o);
    if (lane == 0) g_beta[row] = g_S / (32768.0f * c);
}

// ---------------- R_k += sum_b E[b,k]*beta_b ----------------------------------
__global__ void k_colpass() {
    int t = threadIdx.x;           // 256
    int base = blockIdx.x * 128;   // 256 blocks
    float a0 = 0.0f, a1 = 0.0f;
    for (int r = 0; r < 128; r++) {
        float b = g_beta[base + r];
        size_t idx = (size_t)(base + r) * KK + t;
        a0 += g_bufA[idx] * b;
        a1 += g_bufA[idx + 256] * b;
    }
    atomicAdd(&g_R[t], a0);
    atomicAdd(&g_R[t + 256], a1);
}

// ---------------- loss: q = E*alpha/C_b;  loss_b = -sum_k q*(x/T - lse) --------
__global__ void k_loss() {
    int warp = threadIdx.x >> 5;
    int lane = threadIdx.x & 31;
    int row = blockIdx.x * 8 + warp;
    const float4* pe = (const float4*)(g_bufA + (size_t)row * KK);
    const float4* ps = (const float4*)(g_bufB + (size_t)row * KK);
    const float4* a = (const float4*)g_alpha;
    float lse = g_lse[row];
    float C = 0.0f, Acc = 0.0f;
#pragma unroll
    for (int i = 0; i < 4; i++) {
        float4 e = pe[i * 32 + lane];
        float4 al = a[i * 32 + lane];
        float4 l = ps[i * 32 + lane];
        float q0 = e.x * al.x, q1 = e.y * al.y, q2 = e.z * al.z, q3 = e.w * al.w;
        C += q0 + q1 + q2 + q3;
        Acc += q0 * (l.x * INV_T - lse) + q1 * (l.y * INV_T - lse)
             + q2 * (l.z * INV_T - lse) + q3 * (l.w * INV_T - lse);
    }
#pragma unroll
    for (int o = 16; o > 0; o >>= 1) {
        C += __shfl_xor_sync(0xffffffffu, C, o);
        Acc += __shfl_xor_sync(0xffffffffu, Acc, o);
    }
    if (lane == 0) atomicAdd(&g_loss, -Acc / C);
}

__global__ void k_final(float* __restrict__ out) {
    out[0] = g_loss * (1.0f / 32768.0f);
}

// ---------------- launch -------------------------------------------------------
extern "C" void kernel_launch(void* const* d_in, const int* in_sizes, int n_in,
                              void* d_out, int out_size) {
    // Classify inputs by element count (robust to metadata ordering).
    const float* s = nullptr;
    const float* t = nullptr;
    const float* W_net = nullptr;
    const float* W_proto = nullptr;
    for (int i = 0; i < n_in; i++) {
        long long sz = in_sizes[i];
        if (sz == (long long)BB * DD) {          // 33,554,432: s then t
            if (!s) s = (const float*)d_in[i];
            else if (!t) t = (const float*)d_in[i];
        } else if (sz == (long long)KK * DD) {   // 524,288
            W_net = (const float*)d_in[i];
        } else if (sz == (long long)KK * KK) {   // 262,144
            W_proto = (const float*)d_in[i];
        }
    }
    float* out = (float*)d_out;

    // CRITICAL: resolve real DEVICE addresses of the scratch symbols.
    // (Passing g_bufA etc. directly from host code passes the host shadow
    //  address — on GB300 that silently reads host memory via ATS.)
    float *bufA, *bufB, *bufC, *Cn, *invn;
    cudaGetSymbolAddress((void**)&bufA, g_bufA);
    cudaGetSymbolAddress((void**)&bufB, g_bufB);
    cudaGetSymbolAddress((void**)&bufC, g_bufC);
    cudaGetSymbolAddress((void**)&Cn,   g_Cn);
    cudaGetSymbolAddress((void**)&invn, g_invn);

    dim3 gemmGrid(KK / 128, BB / 128);   // (4, 256)
    dim3 gemmBlk(256);

    k_init<<<1, 512>>>();
    k_proto<<<KK, 128>>>(W_proto);

    // student: Zs = s @ W_net^T ; scores_s = l2norm(Zs) @ Cn^T
    k_sgemm<<<gemmGrid, gemmBlk>>>(s, W_net, bufA, KK, DD, nullptr, 0);
    k_rowinv<<<BB / 8, 256>>>(bufA);
    k_sgemm<<<gemmGrid, gemmBlk>>>(bufA, Cn, bufB, KK, KK, invn, 0);

    // teacher: Zt = t @ W_net^T ; scores_t = l2norm(Zt) @ Cn^T (+ global max)
    k_sgemm<<<gemmGrid, gemmBlk>>>(t, W_net, bufC, KK, DD, nullptr, 0);
    k_rowinv<<<BB / 8, 256>>>(bufC);
    k_sgemm<<<gemmGrid, gemmBlk>>>(bufC, Cn, bufA, KK, KK, invn, 1);

    // log-softmax denominator for student
    k_lse<<<BB / 8, 256>>>();

    // sinkhorn (factor form): E + first colsum
    k_expcol<<<BB / 128, 256>>>();
    k_alpha<<<1, 512>>>(1);
    k_rowpass<<<BB / 8, 256>>>();   // beta1
    k_colpass<<<BB / 128, 256>>>();
    k_alpha<<<1, 512>>>(0);         // alpha2
    k_rowpass<<<BB / 8, 256>>>();   // beta2
    k_colpass<<<BB / 128, 256>>>();
    k_alpha<<<1, 512>>>(0);         // alpha3

    // loss (recomputes C_b with alpha3 == final column normalization)
    k_loss<<<BB / 8, 256>>>();
    k_final<<<1, 1>>>(out);
}

// round 5
// speedup vs baseline: 3.6301x; 3.6301x over previous
#include <cuda_runtime.h>
#include <cuda_bf16.h>
#include <math.h>
#include <stdint.h>

#define BB 32768
#define DD 1024
#define KK 512
#define INV_T 10.0f

// ---------------- scratch (static device globals) ----------------------------
__device__ __align__(16) float g_Z[16777216];     // Z (pre-norm) f32
__device__ __align__(16) float g_Ss[16777216];    // scores_s f32
__device__ __align__(16) float g_E[16777216];     // scores_t -> E f32
__device__ __align__(16) __nv_bfloat16 g_X[33554432];    // s/t bf16
__device__ __align__(16) __nv_bfloat16 g_Zn[16777216];   // normalized Z bf16
__device__ __align__(16) __nv_bfloat16 g_W[524288];      // W_net bf16
__device__ __align__(16) __nv_bfloat16 g_Cn[262144];     // normalized protos bf16
__device__ float g_beta[BB];
__device__ float g_lse[BB];
__device__ float g_R[KK];
__device__ float g_alpha[KK];
__device__ float g_M;
__device__ float g_S;
__device__ float g_loss;

// ---------------- helpers ------------------------------------------------------
__device__ __forceinline__ uint32_t smem_u32(const void* p) {
    uint32_t a;
    asm("{ .reg .u64 t; cvta.to.shared.u64 t, %1; cvt.u32.u64 %0, t; }"
        : "=r"(a) : "l"(p));
    return a;
}
__device__ __forceinline__ void cp_async16(uint32_t saddr, const void* g) {
    asm volatile("cp.async.cg.shared.global [%0], [%1], 16;"
                 :: "r"(saddr), "l"(g) : "memory");
}
__device__ __forceinline__ void ldsm_x4(uint32_t* r, uint32_t addr) {
    asm volatile("ldmatrix.sync.aligned.m8n8.x4.shared.b16 {%0,%1,%2,%3}, [%4];"
                 : "=r"(r[0]), "=r"(r[1]), "=r"(r[2]), "=r"(r[3]) : "r"(addr));
}
__device__ __forceinline__ void mma16816(float* c, const uint32_t* a,
                                         uint32_t b0, uint32_t b1) {
    asm volatile(
        "mma.sync.aligned.m16n8k16.row.col.f32.bf16.bf16.f32 "
        "{%0,%1,%2,%3}, {%4,%5,%6,%7}, {%8,%9}, {%0,%1,%2,%3};"
        : "+f"(c[0]), "+f"(c[1]), "+f"(c[2]), "+f"(c[3])
        : "r"(a[0]), "r"(a[1]), "r"(a[2]), "r"(a[3]), "r"(b0), "r"(b1));
}
#define SWZ(o) ((o) ^ (((o) >> 3) & 0x70))

__device__ __forceinline__ void atomicMaxF(float* addr, float val) {
    int* a = (int*)addr;
    int old = *a;
    while (__int_as_float(old) < val) {
        int assumed = old;
        old = atomicCAS(a, assumed, __float_as_int(val));
        if (old == assumed) break;
    }
}

// ---------------- init ----------------------------------------------------------
__global__ void k_init() {
    int t = threadIdx.x;
    g_R[t] = 0.0f;
    if (t == 0) {
        g_M = __int_as_float(0xff800000);
        g_loss = 0.0f;
    }
}

// ---------------- Cn = l2norm rows of W_proto -> bf16 ---------------------------
__global__ void k_proto(const float* __restrict__ W) {
    int row = blockIdx.x;          // 512
    int t = threadIdx.x;           // 128
    float4 v = ((const float4*)(W + (size_t)row * KK))[t];
    float s = v.x * v.x + v.y * v.y + v.z * v.z + v.w * v.w;
    __shared__ float sm[128];
    sm[t] = s;
    __syncthreads();
    for (int o = 64; o > 0; o >>= 1) {
        if (t < o) sm[t] += sm[t + o];
        __syncthreads();
    }
    float inv = rsqrtf(sm[0]);
    __nv_bfloat162* hp = (__nv_bfloat162*)(g_Cn + (size_t)row * KK + t * 4);
    hp[0] = __halves2bfloat162(__float2bfloat16(v.x * inv), __float2bfloat16(v.y * inv));
    hp[1] = __halves2bfloat162(__float2bfloat16(v.z * inv), __float2bfloat16(v.w * inv));
}

// ---------------- f32 -> bf16 (grid-stride) --------------------------------------
__global__ void k_conv(const float* __restrict__ x, __nv_bfloat16* __restrict__ hd,
                       int n4) {
    int i = blockIdx.x * blockDim.x + threadIdx.x;
    int stride = gridDim.x * blockDim.x;
    for (; i < n4; i += stride) {
        float4 v = ((const float4*)x)[i];
        __nv_bfloat162* hp = (__nv_bfloat162*)(hd + (size_t)i * 4);
        hp[0] = __halves2bfloat162(__float2bfloat16(v.x), __float2bfloat16(v.y));
        hp[1] = __halves2bfloat162(__float2bfloat16(v.z), __float2bfloat16(v.w));
    }
}

// ---------------- row-l2-normalize g_Z, emit bf16 --------------------------------
__global__ void k_normconv() {
    int warp = threadIdx.x >> 5;
    int lane = threadIdx.x & 31;
    int row = blockIdx.x * 8 + warp;
    const float4* p = (const float4*)(g_Z + (size_t)row * KK);
    float4 v[4];
    float s = 0.0f;
#pragma unroll
    for (int i = 0; i < 4; i++) {
        v[i] = p[i * 32 + lane];
        s += v[i].x * v[i].x + v[i].y * v[i].y + v[i].z * v[i].z + v[i].w * v[i].w;
    }
#pragma unroll
    for (int o = 16; o > 0; o >>= 1) s += __shfl_xor_sync(0xffffffffu, s, o);
    float inv = rsqrtf(s);
#pragma unroll
    for (int i = 0; i < 4; i++) {
        size_t off = (size_t)row * KK + i * 128 + lane * 4;
        __nv_bfloat162* hp = (__nv_bfloat162*)(g_Zn + off);
        hp[0] = __halves2bfloat162(__float2bfloat16(v[i].x * inv),
                                   __float2bfloat16(v[i].y * inv));
        hp[1] = __halves2bfloat162(__float2bfloat16(v[i].z * inv),
                                   __float2bfloat16(v[i].w * inv));
    }
}

// ---------------- bf16 mma.sync GEMM (NT): C = A @ B^T ---------------------------
// 128x128 CTA tile, k-tile 64, 3-stage cp.async pipeline, 8 warps (64x32 each).
#define STAGES 3
#define STAGE_BYTES 32768
__global__ void __launch_bounds__(256, 2)
k_gemm(const __nv_bfloat16* __restrict__ A, const __nv_bfloat16* __restrict__ B,
       float* __restrict__ C, int Kd, int doMax) {
    extern __shared__ char smem[];
    __shared__ float wmax[8];

    int tid = threadIdx.x, wid = tid >> 5, lane = tid & 31;
    int m0 = blockIdx.y * 128, n0 = blockIdx.x * 128;
    int wm = wid >> 2, wn = wid & 3;

    uint32_t s_base = smem_u32(smem);
    int NT = Kd >> 6;

    // cp.async loader: A tile 128x64 bf16 (16KB) + B tile (16KB) per stage
    int lrow = tid >> 3, lseg = tid & 7;
    const __nv_bfloat16* gA0 = A + (size_t)(m0 + lrow) * Kd + lseg * 8;
    const __nv_bfloat16* gB0 = B + (size_t)(n0 + lrow) * Kd + lseg * 8;
    auto load = [&](int kt, int st) {
        int kc = kt * 64;
        uint32_t sa = s_base + st * STAGE_BYTES;
#pragma unroll
        for (int p = 0; p < 4; p++) {
            uint32_t so = SWZ((lrow + p * 32) * 128 + lseg * 16);
            cp_async16(sa + so, gA0 + (size_t)p * 32 * Kd + kc);
            cp_async16(sa + 16384 + so, gB0 + (size_t)p * 32 * Kd + kc);
        }
        asm volatile("cp.async.commit_group;" ::: "memory");
    };

    // ldmatrix per-thread base offsets (within tile, stage-relative)
    uint32_t offA[4], offB[2];
    {
        int rA = (lane & 7) + ((lane >> 3) & 1) * 8;
        int sA = (lane >> 4) * 16;
#pragma unroll
        for (int im = 0; im < 4; im++) {
            int row = wm * 64 + im * 16 + rA;
            offA[im] = (uint32_t)(row * 128) | (uint32_t)(sA ^ ((row & 7) << 4));
        }
        int rB = (lane & 7) + ((lane >> 4) & 1) * 8;
        int sB = ((lane >> 3) & 1) * 16;
#pragma unroll
        for (int j = 0; j < 2; j++) {
            int row = wn * 32 + j * 16 + rB;
            offB[j] = 16384u + ((uint32_t)(row * 128) |
                                (uint32_t)(sB ^ ((row & 7) << 4)));
        }
    }

    float acc[4][4][4];
#pragma unroll
    for (int i = 0; i < 4; i++)
#pragma unroll
        for (int j = 0; j < 4; j++)
#pragma unroll
            for (int k = 0; k < 4; k++) acc[i][j][k] = 0.0f;

    load(0, 0);
    load(1, 1);

    for (int kt = 0; kt < NT; kt++) {
        asm volatile("cp.async.wait_group 1;" ::: "memory");
        __syncthreads();
        uint32_t sb = s_base + (uint32_t)(kt % 3) * STAGE_BYTES;
#pragma unroll
        for (int ks = 0; ks < 4; ks++) {
            uint32_t kx = (uint32_t)(ks << 5);
            uint32_t a[4][4], b[2][4];
#pragma unroll
            for (int im = 0; im < 4; im++) ldsm_x4(a[im], sb + (offA[im] ^ kx));
#pragma unroll
            for (int j = 0; j < 2; j++) ldsm_x4(b[j], sb + (offB[j] ^ kx));
#pragma unroll
            for (int im = 0; im < 4; im++)
#pragma unroll
                for (int j = 0; j < 2; j++) {
                    mma16816(acc[im][j * 2 + 0], a[im], b[j][0], b[j][1]);
                    mma16816(acc[im][j * 2 + 1], a[im], b[j][2], b[j][3]);
                }
        }
        if (kt + 2 < NT) load(kt + 2, (kt + 2) % 3);
        else asm volatile("cp.async.commit_group;" ::: "memory");
    }

    // ---- epilogue ----
    float lmax = __int_as_float(0xff800000);
#pragma unroll
    for (int im = 0; im < 4; im++) {
        int m = m0 + wm * 64 + im * 16 + (lane >> 2);
#pragma unroll
        for (int jn = 0; jn < 4; jn++) {
            int n = n0 + wn * 32 + jn * 8 + (lane & 3) * 2;
            float2 lo = make_float2(acc[im][jn][0], acc[im][jn][1]);
            float2 hi = make_float2(acc[im][jn][2], acc[im][jn][3]);
            if (doMax) {
                lmax = fmaxf(lmax, fmaxf(lo.x, lo.y));
                lmax = fmaxf(lmax, fmaxf(hi.x, hi.y));
            }
            *(float2*)(C + (size_t)m * KK + n) = lo;
            *(float2*)(C + (size_t)(m + 8) * KK + n) = hi;
        }
    }
    if (doMax) {
#pragma unroll
        for (int o = 16; o > 0; o >>= 1)
            lmax = fmaxf(lmax, __shfl_xor_sync(0xffffffffu, lmax, o));
        if (lane == 0) wmax[wid] = lmax;
        __syncthreads();
        if (tid == 0) {
            float m2 = wmax[0];
#pragma unroll
            for (int i = 1; i < 8; i++) m2 = fmaxf(m2, wmax[i]);
            atomicMaxF(&g_M, m2);
        }
    }
}

// ---------------- lse[b] of g_Ss / T ----------------------------------------------
__global__ void k_lse() {
    int warp = threadIdx.x >> 5;
    int lane = threadIdx.x & 31;
    int row = blockIdx.x * 8 + warp;
    const float4* p = (const float4*)(g_Ss + (size_t)row * KK);
    float4 v[4];
    float mx = __int_as_float(0xff800000);
#pragma unroll
    for (int i = 0; i < 4; i++) {
        v[i] = p[i * 32 + lane];
        v[i].x *= INV_T; v[i].y *= INV_T; v[i].z *= INV_T; v[i].w *= INV_T;
        mx = fmaxf(mx, fmaxf(fmaxf(v[i].x, v[i].y), fmaxf(v[i].z, v[i].w)));
    }
#pragma unroll
    for (int o = 16; o > 0; o >>= 1) mx = fmaxf(mx, __shfl_xor_sync(0xffffffffu, mx, o));
    float s = 0.0f;
#pragma unroll
    for (int i = 0; i < 4; i++)
        s += expf(v[i].x - mx) + expf(v[i].y - mx) + expf(v[i].z - mx) + expf(v[i].w - mx);
#pragma unroll
    for (int o = 16; o > 0; o >>= 1) s += __shfl_xor_sync(0xffffffffu, s, o);
    if (lane == 0) g_lse[row] = mx + logf(s);
}

// ---------------- E = exp((scores_t - M)/T), col-accumulate R_k --------------------
__global__ void k_expcol() {
    int t = threadIdx.x;           // 256
    int base = blockIdx.x * 128;   // 256 blocks
    float Mv = g_M;
    float a0 = 0.0f, a1 = 0.0f;
    for (int r = 0; r < 128; r++) {
        size_t idx = (size_t)(base + r) * KK + t;
        float e0 = expf((g_E[idx] - Mv) * INV_T);
        g_E[idx] = e0; a0 += e0;
        float e1 = expf((g_E[idx + 256] - Mv) * INV_T);
        g_E[idx + 256] = e1; a1 += e1;
    }
    atomicAdd(&g_R[t], a0);
    atomicAdd(&g_R[t + 256], a1);
}

// ---------------- alpha_k = S / (K * R_k), reset R ---------------------------------
__global__ void k_alpha(int first) {
    int t = threadIdx.x;           // 512
    float Rk = g_R[t];
    __shared__ float sm[512];
    float S;
    if (first) {
        sm[t] = Rk;
        __syncthreads();
        for (int o = 256; o > 0; o >>= 1) {
            if (t < o) sm[t] += sm[t + o];
            __syncthreads();
        }
        S = sm[0];
        if (t == 0) g_S = S;
    } else {
        S = g_S;
    }
    g_alpha[t] = S / (512.0f * Rk);
    g_R[t] = 0.0f;
}

// ---------------- beta_b = S / (B * sum_k E[b,k]*alpha_k) --------------------------
__global__ void k_rowpass() {
    int warp = threadIdx.x >> 5;
    int lane = threadIdx.x & 31;
    int row = blockIdx.x * 8 + warp;
    const float4* p = (const float4*)(g_E + (size_t)row * KK);
    const float4* a = (const float4*)g_alpha;
    float c = 0.0f;
#pragma unroll
    for (int i = 0; i < 4; i++) {
        float4 e = p[i * 32 + lane];
        float4 al = a[i * 32 + lane];
        c += e.x * al.x + e.y * al.y + e.z * al.z + e.w * al.w;
    }
#pragma unroll
    for (int o = 16; o > 0; o >>= 1) c += __shfl_xor_sync(0xffffffffu, c, o);
    if (lane == 0) g_beta[row] = g_S / (32768.0f * c);
}

// ---------------- R_k += sum_b E[b,k]*beta_b ---------------------------------------
__global__ void k_colpass() {
    int t = threadIdx.x;           // 256
    int base = blockIdx.x * 128;
    float a0 = 0.0f, a1 = 0.0f;
    for (int r = 0; r < 128; r++) {
        float b = g_beta[base + r];
        size_t idx = (size_t)(base + r) * KK + t;
        a0 += g_E[idx] * b;
        a1 += g_E[idx + 256] * b;
    }
    atomicAdd(&g_R[t], a0);
    atomicAdd(&g_R[t + 256], a1);
}

// ---------------- loss --------------------------------------------------------------
__global__ void k_loss() {
    int warp = threadIdx.x >> 5;
    int lane = threadIdx.x & 31;
    int row = blockIdx.x * 8 + warp;
    const float4* pe = (const float4*)(g_E + (size_t)row * KK);
    const float4* ps = (const float4*)(g_Ss + (size_t)row * KK);
    const float4* a = (const float4*)g_alpha;
    float lse = g_lse[row];
    float C = 0.0f, Acc = 0.0f;
#pragma unroll
    for (int i = 0; i < 4; i++) {
        float4 e = pe[i * 32 + lane];
        float4 al = a[i * 32 + lane];
        float4 l = ps[i * 32 + lane];
        float q0 = e.x * al.x, q1 = e.y * al.y, q2 = e.z * al.z, q3 = e.w * al.w;
        C += q0 + q1 + q2 + q3;
        Acc += q0 * (l.x * INV_T - lse) + q1 * (l.y * INV_T - lse)
             + q2 * (l.z * INV_T - lse) + q3 * (l.w * INV_T - lse);
    }
#pragma unroll
    for (int o = 16; o > 0; o >>= 1) {
        C += __shfl_xor_sync(0xffffffffu, C, o);
        Acc += __shfl_xor_sync(0xffffffffu, Acc, o);
    }
    if (lane == 0) atomicAdd(&g_loss, -Acc / C);
}

__global__ void k_final(float* __restrict__ out) {
    out[0] = g_loss * (1.0f / 32768.0f);
}

// ---------------- launch -------------------------------------------------------------
#define GEMM_SMEM (STAGES * STAGE_BYTES)

extern "C" void kernel_launch(void* const* d_in, const int* in_sizes, int n_in,
                              void* d_out, int out_size) {
    const float* s = nullptr;
    const float* t = nullptr;
    const float* W_net = nullptr;
    const float* W_proto = nullptr;
    for (int i = 0; i < n_in; i++) {
        long long sz = in_sizes[i];
        if (sz == (long long)BB * DD) {
            if (!s) s = (const float*)d_in[i];
            else if (!t) t = (const float*)d_in[i];
        } else if (sz == (long long)KK * DD) {
            W_net = (const float*)d_in[i];
        } else if (sz == (long long)KK * KK) {
            W_proto = (const float*)d_in[i];
        }
    }
    float* out = (float*)d_out;

    // real DEVICE addresses of scratch symbols
    float *Z, *Ss, *E;
    __nv_bfloat16 *X, *Zn, *W, *Cn;
    cudaGetSymbolAddress((void**)&Z, g_Z);
    cudaGetSymbolAddress((void**)&Ss, g_Ss);
    cudaGetSymbolAddress((void**)&E, g_E);
    cudaGetSymbolAddress((void**)&X, g_X);
    cudaGetSymbolAddress((void**)&Zn, g_Zn);
    cudaGetSymbolAddress((void**)&W, g_W);
    cudaGetSymbolAddress((void**)&Cn, g_Cn);

    cudaFuncSetAttribute(k_gemm, cudaFuncAttributeMaxDynamicSharedMemorySize, GEMM_SMEM);

    dim3 gg(KK / 128, BB / 128);   // (4, 256)

    k_init<<<1, 512>>>();
    k_proto<<<KK, 128>>>(W_proto);
    k_conv<<<512, 256>>>(W_net, W, (KK * DD) / 4);

    // student branch
    k_conv<<<8192, 256>>>(s, X, (BB * DD) / 4);
    k_gemm<<<gg, 256, GEMM_SMEM>>>(X, W, Z, DD, 0);
    k_normconv<<<BB / 8, 256>>>();
    k_gemm<<<gg, 256, GEMM_SMEM>>>(Zn, Cn, Ss, KK, 0);

    // teacher branch
    k_conv<<<8192, 256>>>(t, X, (BB * DD) / 4);
    k_gemm<<<gg, 256, GEMM_SMEM>>>(X, W, Z, DD, 0);
    k_normconv<<<BB / 8, 256>>>();
    k_gemm<<<gg, 256, GEMM_SMEM>>>(Zn, Cn, E, KK, 1);

    // student log-softmax denominator
    k_lse<<<BB / 8, 256>>>();

    // sinkhorn (factor form)
    k_expcol<<<BB / 128, 256>>>();
    k_alpha<<<1, 512>>>(1);
    k_rowpass<<<BB / 8, 256>>>();
    k_colpass<<<BB / 128, 256>>>();
    k_alpha<<<1, 512>>>(0);
    k_rowpass<<<BB / 8, 256>>>();
    k_colpass<<<BB / 128, 256>>>();
    k_alpha<<<1, 512>>>(0);

    k_loss<<<BB / 8, 256>>>();
    k_final<<<1, 1>>>(out);
}

// round 6
// speedup vs baseline: 4.3186x; 1.1897x over previous
#include <cuda_runtime.h>
#include <cuda_bf16.h>
#include <math.h>
#include <stdint.h>

#define BB 32768
#define DD 1024
#define KK 512
#define INV_T 10.0f

// ---------------- scratch (static device globals) ----------------------------
__device__ __align__(16) float g_Ss[16777216];    // scores_s f32
__device__ __align__(16) float g_E[16777216];     // E = exp((score_t-1)*10) f32
__device__ __align__(16) __nv_bfloat16 g_X[33554432];    // s/t bf16
__device__ __align__(16) __nv_bfloat16 g_Zb[16777216];   // Z bf16 (unnormalized)
__device__ __align__(16) __nv_bfloat16 g_W[524288];      // W_net bf16
__device__ __align__(16) __nv_bfloat16 g_Cn[262144];     // normalized protos bf16
__device__ float g_ss[BB];      // row sumsq of Z
__device__ float g_invn[BB];    // 1/||Z row||
__device__ float g_beta[BB];
__device__ float g_R[KK];
__device__ float g_alpha[KK];
__device__ float g_S;
__device__ float g_loss;

// ---------------- helpers ------------------------------------------------------
__device__ __forceinline__ uint32_t smem_u32(const void* p) {
    uint32_t a;
    asm("{ .reg .u64 t; cvta.to.shared.u64 t, %1; cvt.u32.u64 %0, t; }"
        : "=r"(a) : "l"(p));
    return a;
}
__device__ __forceinline__ void cp_async16(uint32_t saddr, const void* g) {
    asm volatile("cp.async.cg.shared.global [%0], [%1], 16;"
                 :: "r"(saddr), "l"(g) : "memory");
}
__device__ __forceinline__ void ldsm_x4(uint32_t* r, uint32_t addr) {
    asm volatile("ldmatrix.sync.aligned.m8n8.x4.shared.b16 {%0,%1,%2,%3}, [%4];"
                 : "=r"(r[0]), "=r"(r[1]), "=r"(r[2]), "=r"(r[3]) : "r"(addr));
}
__device__ __forceinline__ void mma16816(float* c, const uint32_t* a,
                                         uint32_t b0, uint32_t b1) {
    asm volatile(
        "mma.sync.aligned.m16n8k16.row.col.f32.bf16.bf16.f32 "
        "{%0,%1,%2,%3}, {%4,%5,%6,%7}, {%8,%9}, {%0,%1,%2,%3};"
        : "+f"(c[0]), "+f"(c[1]), "+f"(c[2]), "+f"(c[3])
        : "r"(a[0]), "r"(a[1]), "r"(a[2]), "r"(a[3]), "r"(b0), "r"(b1));
}
#define SWZ(o) ((o) ^ (((o) >> 3) & 0x70))

// fast e^x on the FMA pipe (exp2-based, degree-6 poly, rel err ~6e-8).
// Valid for x in roughly [-80, 80]; we use x in [-25, 1].
__device__ __forceinline__ float fexp(float x) {
    float y = x * 1.4426950408889634f;          // log2(e)
    float t = y + 12582912.0f;                  // round-to-nearest-even
    int e = __float_as_int(t) - 0x4B400000;     // = rint(y)
    float f = y - (t - 12582912.0f);            // |f| <= 0.5
    float p = 1.5403530e-4f;
    p = fmaf(p, f, 1.3333558e-3f);
    p = fmaf(p, f, 9.6181291e-3f);
    p = fmaf(p, f, 5.5504109e-2f);
    p = fmaf(p, f, 2.4022651e-1f);
    p = fmaf(p, f, 6.9314718e-1f);
    p = fmaf(p, f, 1.0f);
    return p * __int_as_float((e + 127) << 23);
}

// ---------------- init ----------------------------------------------------------
__global__ void k_init() {
    int i = blockIdx.x * blockDim.x + threadIdx.x;   // 64*512 = 32768
    g_ss[i] = 0.0f;
    if (i < KK) g_R[i] = 0.0f;
    if (i == 0) g_loss = 0.0f;
}

// ---------------- Cn = l2norm rows of W_proto -> bf16 ---------------------------
__global__ void k_proto(const float* __restrict__ W) {
    int row = blockIdx.x;          // 512
    int t = threadIdx.x;           // 128
    float4 v = ((const float4*)(W + (size_t)row * KK))[t];
    float s = v.x * v.x + v.y * v.y + v.z * v.z + v.w * v.w;
    __shared__ float sm[128];
    sm[t] = s;
    __syncthreads();
    for (int o = 64; o > 0; o >>= 1) {
        if (t < o) sm[t] += sm[t + o];
        __syncthreads();
    }
    float inv = rsqrtf(sm[0]);
    __nv_bfloat162* hp = (__nv_bfloat162*)(g_Cn + (size_t)row * KK + t * 4);
    hp[0] = __halves2bfloat162(__float2bfloat16(v.x * inv), __float2bfloat16(v.y * inv));
    hp[1] = __halves2bfloat162(__float2bfloat16(v.z * inv), __float2bfloat16(v.w * inv));
}

// ---------------- f32 -> bf16 (grid-stride) --------------------------------------
__global__ void k_conv(const float* __restrict__ x, __nv_bfloat16* __restrict__ hd,
                       int n4) {
    int i = blockIdx.x * blockDim.x + threadIdx.x;
    int stride = gridDim.x * blockDim.x;
    for (; i < n4; i += stride) {
        float4 v = ((const float4*)x)[i];
        __nv_bfloat162* hp = (__nv_bfloat162*)(hd + (size_t)i * 4);
        hp[0] = __halves2bfloat162(__float2bfloat16(v.x), __float2bfloat16(v.y));
        hp[1] = __halves2bfloat162(__float2bfloat16(v.z), __float2bfloat16(v.w));
    }
}

// ---------------- invn = rsqrt(ss); ss = 0 ----------------------------------------
__global__ void k_inv() {
    int i = blockIdx.x * blockDim.x + threadIdx.x;
    g_invn[i] = rsqrtf(g_ss[i]);
    g_ss[i] = 0.0f;
}

// ---------------- bf16 mma.sync GEMM (NT): 128x128 tile, k-tile 64, 3 stages -----
// mode 0: out = bf16(acc), accumulate row sumsq into g_ss (gemm1)
// mode 1: out = f32(acc * invn[m])                         (gemm2 student)
// mode 2: out = f32(fexp((acc*invn[m] - 1) * 10))          (gemm2 teacher)
#define STAGES 3
#define STAGE_BYTES 32768
__global__ void __launch_bounds__(256, 2)
k_gemm(const __nv_bfloat16* __restrict__ A, const __nv_bfloat16* __restrict__ B,
       void* __restrict__ Cout, int Kd, int mode) {
    extern __shared__ char smem[];

    int tid = threadIdx.x, wid = tid >> 5, lane = tid & 31;
    int m0 = blockIdx.y * 128, n0 = blockIdx.x * 128;
    int wm = wid >> 2, wn = wid & 3;

    uint32_t s_base = smem_u32(smem);
    int NT = Kd >> 6;

    int lrow = tid >> 3, lseg = tid & 7;
    const __nv_bfloat16* gA0 = A + (size_t)(m0 + lrow) * Kd + lseg * 8;
    const __nv_bfloat16* gB0 = B + (size_t)(n0 + lrow) * Kd + lseg * 8;
    auto load = [&](int kt, int st) {
        int kc = kt * 64;
        uint32_t sa = s_base + st * STAGE_BYTES;
#pragma unroll
        for (int p = 0; p < 4; p++) {
            uint32_t so = SWZ((lrow + p * 32) * 128 + lseg * 16);
            cp_async16(sa + so, gA0 + (size_t)p * 32 * Kd + kc);
            cp_async16(sa + 16384 + so, gB0 + (size_t)p * 32 * Kd + kc);
        }
        asm volatile("cp.async.commit_group;" ::: "memory");
    };

    uint32_t offA[4], offB[2];
    {
        int rA = (lane & 7) + ((lane >> 3) & 1) * 8;
        int sA = (lane >> 4) * 16;
#pragma unroll
        for (int im = 0; im < 4; im++) {
            int row = wm * 64 + im * 16 + rA;
            offA[im] = (uint32_t)(row * 128) | (uint32_t)(sA ^ ((row & 7) << 4));
        }
        int rB = (lane & 7) + ((lane >> 4) & 1) * 8;
        int sB = ((lane >> 3) & 1) * 16;
#pragma unroll
        for (int j = 0; j < 2; j++) {
            int row = wn * 32 + j * 16 + rB;
            offB[j] = 16384u + ((uint32_t)(row * 128) |
                                (uint32_t)(sB ^ ((row & 7) << 4)));
        }
    }

    float acc[4][4][4];
#pragma unroll
    for (int i = 0; i < 4; i++)
#pragma unroll
        for (int j = 0; j < 4; j++)
#pragma unroll
            for (int k = 0; k < 4; k++) acc[i][j][k] = 0.0f;

    load(0, 0);
    load(1, 1);

    for (int kt = 0; kt < NT; kt++) {
        asm volatile("cp.async.wait_group 1;" ::: "memory");
        __syncthreads();
        uint32_t sb = s_base + (uint32_t)(kt % 3) * STAGE_BYTES;
#pragma unroll
        for (int ks = 0; ks < 4; ks++) {
            uint32_t kx = (uint32_t)(ks << 5);
            uint32_t a[4][4], b[2][4];
#pragma unroll
            for (int im = 0; im < 4; im++) ldsm_x4(a[im], sb + (offA[im] ^ kx));
#pragma unroll
            for (int j = 0; j < 2; j++) ldsm_x4(b[j], sb + (offB[j] ^ kx));
#pragma unroll
            for (int im = 0; im < 4; im++)
#pragma unroll
                for (int j = 0; j < 2; j++) {
                    mma16816(acc[im][j * 2 + 0], a[im], b[j][0], b[j][1]);
                    mma16816(acc[im][j * 2 + 1], a[im], b[j][2], b[j][3]);
                }
        }
        if (kt + 2 < NT) load(kt + 2, (kt + 2) % 3);
        else asm volatile("cp.async.commit_group;" ::: "memory");
    }

    // ---- epilogue ----
    if (mode == 0) {
        __nv_bfloat16* C = (__nv_bfloat16*)Cout;
#pragma unroll
        for (int im = 0; im < 4; im++) {
            int m = m0 + wm * 64 + im * 16 + (lane >> 2);
            float s0 = 0.0f, s1 = 0.0f;
#pragma unroll
            for (int jn = 0; jn < 4; jn++) {
                int n = n0 + wn * 32 + jn * 8 + (lane & 3) * 2;
                float c0 = acc[im][jn][0], c1 = acc[im][jn][1];
                float c2 = acc[im][jn][2], c3 = acc[im][jn][3];
                s0 += c0 * c0 + c1 * c1;
                s1 += c2 * c2 + c3 * c3;
                *(__nv_bfloat162*)(C + (size_t)m * KK + n) =
                    __halves2bfloat162(__float2bfloat16(c0), __float2bfloat16(c1));
                *(__nv_bfloat162*)(C + (size_t)(m + 8) * KK + n) =
                    __halves2bfloat162(__float2bfloat16(c2), __float2bfloat16(c3));
            }
            s0 += __shfl_xor_sync(0xffffffffu, s0, 1);
            s0 += __shfl_xor_sync(0xffffffffu, s0, 2);
            s1 += __shfl_xor_sync(0xffffffffu, s1, 1);
            s1 += __shfl_xor_sync(0xffffffffu, s1, 2);
            if ((lane & 3) == 0) {
                atomicAdd(&g_ss[m], s0);
                atomicAdd(&g_ss[m + 8], s1);
            }
        }
    } else {
        float* C = (float*)Cout;
#pragma unroll
        for (int im = 0; im < 4; im++) {
            int m = m0 + wm * 64 + im * 16 + (lane >> 2);
            float i0 = g_invn[m], i1 = g_invn[m + 8];
#pragma unroll
            for (int jn = 0; jn < 4; jn++) {
                int n = n0 + wn * 32 + jn * 8 + (lane & 3) * 2;
                float2 lo = make_float2(acc[im][jn][0] * i0, acc[im][jn][1] * i0);
                float2 hi = make_float2(acc[im][jn][2] * i1, acc[im][jn][3] * i1);
                if (mode == 2) {
                    lo.x = fexp((lo.x - 1.0f) * INV_T);
                    lo.y = fexp((lo.y - 1.0f) * INV_T);
                    hi.x = fexp((hi.x - 1.0f) * INV_T);
                    hi.y = fexp((hi.y - 1.0f) * INV_T);
                }
                *(float2*)(C + (size_t)m * KK + n) = lo;
                *(float2*)(C + (size_t)(m + 8) * KK + n) = hi;
            }
        }
    }
}

// ---------------- R_k = colsums of E ------------------------------------------------
__global__ void k_colsum() {
    int t = threadIdx.x;           // 256
    int base = blockIdx.x * 128;   // 256 blocks
    float a0 = 0.0f, a1 = 0.0f;
    for (int r = 0; r < 128; r++) {
        size_t idx = (size_t)(base + r) * KK + t;
        a0 += g_E[idx];
        a1 += g_E[idx + 256];
    }
    atomicAdd(&g_R[t], a0);
    atomicAdd(&g_R[t + 256], a1);
}

// ---------------- alpha_k = S / (K * R_k), reset R -----------------------------------
__global__ void k_alpha(int first) {
    int t = threadIdx.x;           // 512
    float Rk = g_R[t];
    __shared__ float sm[512];
    float S;
    if (first) {
        sm[t] = Rk;
        __syncthreads();
        for (int o = 256; o > 0; o >>= 1) {
            if (t < o) sm[t] += sm[t + o];
            __syncthreads();
        }
        S = sm[0];
        if (t == 0) g_S = S;
    } else {
        S = g_S;
    }
    g_alpha[t] = S / (512.0f * Rk);
    g_R[t] = 0.0f;
}

// ---------------- beta_b = S / (B * sum_k E[b,k]*alpha_k) ----------------------------
__global__ void k_rowpass() {
    int warp = threadIdx.x >> 5;
    int lane = threadIdx.x & 31;
    int row = blockIdx.x * 8 + warp;
    const float4* p = (const float4*)(g_E + (size_t)row * KK);
    const float4* a = (const float4*)g_alpha;
    float c = 0.0f;
#pragma unroll
    for (int i = 0; i < 4; i++) {
        float4 e = p[i * 32 + lane];
        float4 al = a[i * 32 + lane];
        c += e.x * al.x + e.y * al.y + e.z * al.z + e.w * al.w;
    }
#pragma unroll
    for (int o = 16; o > 0; o >>= 1) c += __shfl_xor_sync(0xffffffffu, c, o);
    if (lane == 0) g_beta[row] = g_S / (32768.0f * c);
}

// ---------------- R_k += sum_b E[b,k]*beta_b ------------------------------------------
__global__ void k_colpass() {
    int t = threadIdx.x;           // 256
    int base = blockIdx.x * 128;
    float a0 = 0.0f, a1 = 0.0f;
    for (int r = 0; r < 128; r++) {
        float b = g_beta[base + r];
        size_t idx = (size_t)(base + r) * KK + t;
        a0 += g_E[idx] * b;
        a1 += g_E[idx + 256] * b;
    }
    atomicAdd(&g_R[t], a0);
    atomicAdd(&g_R[t + 256], a1);
}

// ---------------- fused lse + loss -----------------------------------------------------
// per row: arg = Ss*10; lse = max + log(sum fexp(arg-max));
// q = E*alpha; C = sum q; Acc = sum q*arg; loss_b = -(Acc - lse*C)/C
__global__ void k_loss() {
    int warp = threadIdx.x >> 5;
    int lane = threadIdx.x & 31;
    int row = blockIdx.x * 8 + warp;
    const float4* pe = (const float4*)(g_E + (size_t)row * KK);
    const float4* ps = (const float4*)(g_Ss + (size_t)row * KK);
    const float4* a = (const float4*)g_alpha;
    float4 e[4], al[4], v[4];
    float mx = __int_as_float(0xff800000);
#pragma unroll
    for (int i = 0; i < 4; i++) {
        e[i] = pe[i * 32 + lane];
        al[i] = a[i * 32 + lane];
        v[i] = ps[i * 32 + lane];
        v[i].x *= INV_T; v[i].y *= INV_T; v[i].z *= INV_T; v[i].w *= INV_T;
        mx = fmaxf(mx, fmaxf(fmaxf(v[i].x, v[i].y), fmaxf(v[i].z, v[i].w)));
    }
#pragma unroll
    for (int o = 16; o > 0; o >>= 1) mx = fmaxf(mx, __shfl_xor_sync(0xffffffffu, mx, o));
    float se = 0.0f, C = 0.0f, Acc = 0.0f;
#pragma unroll
    for (int i = 0; i < 4; i++) {
        se += fexp(v[i].x - mx) + fexp(v[i].y - mx) + fexp(v[i].z - mx) + fexp(v[i].w - mx);
        float q0 = e[i].x * al[i].x, q1 = e[i].y * al[i].y;
        float q2 = e[i].z * al[i].z, q3 = e[i].w * al[i].w;
        C += q0 + q1 + q2 + q3;
        Acc += q0 * v[i].x + q1 * v[i].y + q2 * v[i].z + q3 * v[i].w;
    }
#pragma unroll
    for (int o = 16; o > 0; o >>= 1) {
        se += __shfl_xor_sync(0xffffffffu, se, o);
        C += __shfl_xor_sync(0xffffffffu, C, o);
        Acc += __shfl_xor_sync(0xffffffffu, Acc, o);
    }
    if (lane == 0) {
        float lse = mx + logf(se);
        atomicAdd(&g_loss, -(Acc - lse * C) / C);
    }
}

__global__ void k_final(float* __restrict__ out) {
    out[0] = g_loss * (1.0f / 32768.0f);
}

// ---------------- launch ---------------------------------------------------------------
#define GEMM_SMEM (STAGES * STAGE_BYTES)

extern "C" void kernel_launch(void* const* d_in, const int* in_sizes, int n_in,
                              void* d_out, int out_size) {
    const float* s = nullptr;
    const float* t = nullptr;
    const float* W_net = nullptr;
    const float* W_proto = nullptr;
    for (int i = 0; i < n_in; i++) {
        long long sz = in_sizes[i];
        if (sz == (long long)BB * DD) {
            if (!s) s = (const float*)d_in[i];
            else if (!t) t = (const float*)d_in[i];
        } else if (sz == (long long)KK * DD) {
            W_net = (const float*)d_in[i];
        } else if (sz == (long long)KK * KK) {
            W_proto = (const float*)d_in[i];
        }
    }
    float* out = (float*)d_out;

    float *Ss, *E;
    __nv_bfloat16 *X, *Zb, *W, *Cn;
    cudaGetSymbolAddress((void**)&Ss, g_Ss);
    cudaGetSymbolAddress((void**)&E, g_E);
    cudaGetSymbolAddress((void**)&X, g_X);
    cudaGetSymbolAddress((void**)&Zb, g_Zb);
    cudaGetSymbolAddress((void**)&W, g_W);
    cudaGetSymbolAddress((void**)&Cn, g_Cn);

    cudaFuncSetAttribute(k_gemm, cudaFuncAttributeMaxDynamicSharedMemorySize, GEMM_SMEM);

    dim3 gg(KK / 128, BB / 128);   // (4, 256)

    k_init<<<BB / 512, 512>>>();
    k_proto<<<KK, 128>>>(W_proto);
    k_conv<<<512, 256>>>(W_net, W, (KK * DD) / 4);

    // student branch: Zb = s@W^T (bf16, +sumsq); invn; Ss = invn*(Zb@Cn^T)
    k_conv<<<8192, 256>>>(s, X, (BB * DD) / 4);
    k_gemm<<<gg, 256, GEMM_SMEM>>>(X, W, Zb, DD, 0);
    k_inv<<<BB / 256, 256>>>();
    k_gemm<<<gg, 256, GEMM_SMEM>>>(Zb, Cn, Ss, KK, 1);

    // teacher branch: E = fexp((invn*(Zb@Cn^T) - 1)*10)
    k_conv<<<8192, 256>>>(t, X, (BB * DD) / 4);
    k_gemm<<<gg, 256, GEMM_SMEM>>>(X, W, Zb, DD, 0);
    k_inv<<<BB / 256, 256>>>();
    k_gemm<<<gg, 256, GEMM_SMEM>>>(Zb, Cn, E, KK, 2);

    // sinkhorn (factor form)
    k_colsum<<<BB / 128, 256>>>();
    k_alpha<<<1, 512>>>(1);
    k_rowpass<<<BB / 8, 256>>>();
    k_colpass<<<BB / 128, 256>>>();
    k_alpha<<<1, 512>>>(0);
    k_rowpass<<<BB / 8, 256>>>();
    k_colpass<<<BB / 128, 256>>>();
    k_alpha<<<1, 512>>>(0);

    // fused lse + loss
    k_loss<<<BB / 8, 256>>>();
    k_final<<<1, 1>>>(out);
}

// round 7
// speedup vs baseline: 4.7948x; 1.1103x over previous
#include <cuda_runtime.h>
#include <cuda_bf16.h>
#include <math.h>
#include <stdint.h>

#define BB 32768
#define DD 1024
#define KK 512
#define INV_T 10.0f

// ---------------- scratch (static device globals) ----------------------------
__device__ __align__(16) __nv_bfloat16 g_Ss[16777216];   // scores_s bf16
__device__ __align__(16) __nv_bfloat16 g_E[16777216];    // E bf16
__device__ __align__(16) __nv_bfloat16 g_X[33554432];    // s/t bf16
__device__ __align__(16) __nv_bfloat16 g_Zb[16777216];   // Z bf16 (unnormalized)
__device__ __align__(16) __nv_bfloat16 g_W[524288];      // W_net bf16
__device__ __align__(16) __nv_bfloat16 g_Cn[262144];     // normalized protos bf16
__device__ float g_ss[BB];      // row sumsq of Z
__device__ float g_invn[BB];    // 1/||Z row||
__device__ float g_R[KK];
__device__ float g_alpha[KK];
__device__ float g_S;
__device__ float g_loss;

// ---------------- helpers ------------------------------------------------------
__device__ __forceinline__ uint32_t smem_u32(const void* p) {
    uint32_t a;
    asm("{ .reg .u64 t; cvta.to.shared.u64 t, %1; cvt.u32.u64 %0, t; }"
        : "=r"(a) : "l"(p));
    return a;
}
__device__ __forceinline__ void cp_async16(uint32_t saddr, const void* g) {
    asm volatile("cp.async.cg.shared.global [%0], [%1], 16;"
                 :: "r"(saddr), "l"(g) : "memory");
}
__device__ __forceinline__ void ldsm_x4(uint32_t* r, uint32_t addr) {
    asm volatile("ldmatrix.sync.aligned.m8n8.x4.shared.b16 {%0,%1,%2,%3}, [%4];"
                 : "=r"(r[0]), "=r"(r[1]), "=r"(r[2]), "=r"(r[3]) : "r"(addr));
}
__device__ __forceinline__ void mma16816(float* c, const uint32_t* a,
                                         uint32_t b0, uint32_t b1) {
    asm volatile(
        "mma.sync.aligned.m16n8k16.row.col.f32.bf16.bf16.f32 "
        "{%0,%1,%2,%3}, {%4,%5,%6,%7}, {%8,%9}, {%0,%1,%2,%3};"
        : "+f"(c[0]), "+f"(c[1]), "+f"(c[2]), "+f"(c[3])
        : "r"(a[0]), "r"(a[1]), "r"(a[2]), "r"(a[3]), "r"(b0), "r"(b1));
}
#define SWZ(o) ((o) ^ (((o) >> 3) & 0x70))

// fast e^x on the FMA pipe (exp2-based, degree-6 poly, rel err ~6e-8)
__device__ __forceinline__ float fexp(float x) {
    float y = x * 1.4426950408889634f;
    float t = y + 12582912.0f;
    int e = __float_as_int(t) - 0x4B400000;
    float f = y - (t - 12582912.0f);
    float p = 1.5403530e-4f;
    p = fmaf(p, f, 1.3333558e-3f);
    p = fmaf(p, f, 9.6181291e-3f);
    p = fmaf(p, f, 5.5504109e-2f);
    p = fmaf(p, f, 2.4022651e-1f);
    p = fmaf(p, f, 6.9314718e-1f);
    p = fmaf(p, f, 1.0f);
    return p * __int_as_float((e + 127) << 23);
}

// ---------------- init ----------------------------------------------------------
__global__ void k_init() {
    int i = blockIdx.x * blockDim.x + threadIdx.x;
    g_ss[i] = 0.0f;
    if (i < KK) g_R[i] = 0.0f;
    if (i == 0) g_loss = 0.0f;
}

// ---------------- Cn = l2norm rows of W_proto -> bf16 ---------------------------
__global__ void k_proto(const float* __restrict__ W) {
    int row = blockIdx.x;
    int t = threadIdx.x;
    float4 v = ((const float4*)(W + (size_t)row * KK))[t];
    float s = v.x * v.x + v.y * v.y + v.z * v.z + v.w * v.w;
    __shared__ float sm[128];
    sm[t] = s;
    __syncthreads();
    for (int o = 64; o > 0; o >>= 1) {
        if (t < o) sm[t] += sm[t + o];
        __syncthreads();
    }
    float inv = rsqrtf(sm[0]);
    __nv_bfloat162* hp = (__nv_bfloat162*)(g_Cn + (size_t)row * KK + t * 4);
    hp[0] = __halves2bfloat162(__float2bfloat16(v.x * inv), __float2bfloat16(v.y * inv));
    hp[1] = __halves2bfloat162(__float2bfloat16(v.z * inv), __float2bfloat16(v.w * inv));
}

// ---------------- f32 -> bf16 (grid-stride) --------------------------------------
__global__ void k_conv(const float* __restrict__ x, __nv_bfloat16* __restrict__ hd,
                       int n4) {
    int i = blockIdx.x * blockDim.x + threadIdx.x;
    int stride = gridDim.x * blockDim.x;
    for (; i < n4; i += stride) {
        float4 v = ((const float4*)x)[i];
        __nv_bfloat162* hp = (__nv_bfloat162*)(hd + (size_t)i * 4);
        hp[0] = __halves2bfloat162(__float2bfloat16(v.x), __float2bfloat16(v.y));
        hp[1] = __halves2bfloat162(__float2bfloat16(v.z), __float2bfloat16(v.w));
    }
}

// ---------------- invn = rsqrt(ss); ss = 0 ----------------------------------------
__global__ void k_inv() {
    int i = blockIdx.x * blockDim.x + threadIdx.x;
    g_invn[i] = rsqrtf(g_ss[i]);
    g_ss[i] = 0.0f;
}

// ---------------- bf16 mma.sync GEMM (NT): 128x128 tile, k-tile 64, 3 stages -----
// mode 0: out = bf16(acc), accumulate row sumsq into g_ss        (gemm1)
// mode 1: out = bf16(acc * invn[m])                              (gemm2 student)
// mode 2: out = bf16(fexp((acc*invn[m]-1)*10)), colsums -> g_R   (gemm2 teacher)
#define STAGES 3
#define STAGE_BYTES 32768
__global__ void __launch_bounds__(256, 2)
k_gemm(const __nv_bfloat16* __restrict__ A, const __nv_bfloat16* __restrict__ B,
       __nv_bfloat16* __restrict__ C, int Kd, int mode) {
    extern __shared__ char smem[];
    __shared__ float scp[2][128];

    int tid = threadIdx.x, wid = tid >> 5, lane = tid & 31;
    int m0 = blockIdx.y * 128, n0 = blockIdx.x * 128;
    int wm = wid >> 2, wn = wid & 3;

    uint32_t s_base = smem_u32(smem);
    int NT = Kd >> 6;

    int lrow = tid >> 3, lseg = tid & 7;
    const __nv_bfloat16* gA0 = A + (size_t)(m0 + lrow) * Kd + lseg * 8;
    const __nv_bfloat16* gB0 = B + (size_t)(n0 + lrow) * Kd + lseg * 8;
    auto load = [&](int kt, int st) {
        int kc = kt * 64;
        uint32_t sa = s_base + st * STAGE_BYTES;
#pragma unroll
        for (int p = 0; p < 4; p++) {
            uint32_t so = SWZ((lrow + p * 32) * 128 + lseg * 16);
            cp_async16(sa + so, gA0 + (size_t)p * 32 * Kd + kc);
            cp_async16(sa + 16384 + so, gB0 + (size_t)p * 32 * Kd + kc);
        }
        asm volatile("cp.async.commit_group;" ::: "memory");
    };

    uint32_t offA[4], offB[2];
    {
        int rA = (lane & 7) + ((lane >> 3) & 1) * 8;
        int sA = (lane >> 4) * 16;
#pragma unroll
        for (int im = 0; im < 4; im++) {
            int row = wm * 64 + im * 16 + rA;
            offA[im] = (uint32_t)(row * 128) | (uint32_t)(sA ^ ((row & 7) << 4));
        }
        int rB = (lane & 7) + ((lane >> 4) & 1) * 8;
        int sB = ((lane >> 3) & 1) * 16;
#pragma unroll
        for (int j = 0; j < 2; j++) {
            int row = wn * 32 + j * 16 + rB;
            offB[j] = 16384u + ((uint32_t)(row * 128) |
                                (uint32_t)(sB ^ ((row & 7) << 4)));
        }
    }

    float acc[4][4][4];
#pragma unroll
    for (int i = 0; i < 4; i++)
#pragma unroll
        for (int j = 0; j < 4; j++)
#pragma unroll
            for (int k = 0; k < 4; k++) acc[i][j][k] = 0.0f;

    load(0, 0);
    load(1, 1);

    for (int kt = 0; kt < NT; kt++) {
        asm volatile("cp.async.wait_group 1;" ::: "memory");
        __syncthreads();
        uint32_t sb = s_base + (uint32_t)(kt % 3) * STAGE_BYTES;
#pragma unroll
        for (int ks = 0; ks < 4; ks++) {
            uint32_t kx = (uint32_t)(ks << 5);
            uint32_t a[4][4], b[2][4];
#pragma unroll
            for (int im = 0; im < 4; im++) ldsm_x4(a[im], sb + (offA[im] ^ kx));
#pragma unroll
            for (int j = 0; j < 2; j++) ldsm_x4(b[j], sb + (offB[j] ^ kx));
#pragma unroll
            for (int im = 0; im < 4; im++)
#pragma unroll
                for (int j = 0; j < 2; j++) {
                    mma16816(acc[im][j * 2 + 0], a[im], b[j][0], b[j][1]);
                    mma16816(acc[im][j * 2 + 1], a[im], b[j][2], b[j][3]);
                }
        }
        if (kt + 2 < NT) load(kt + 2, (kt + 2) % 3);
        else asm volatile("cp.async.commit_group;" ::: "memory");
    }

    // ---- epilogue ----
    if (mode == 0) {
#pragma unroll
        for (int im = 0; im < 4; im++) {
            int m = m0 + wm * 64 + im * 16 + (lane >> 2);
            float s0 = 0.0f, s1 = 0.0f;
#pragma unroll
            for (int jn = 0; jn < 4; jn++) {
                int n = n0 + wn * 32 + jn * 8 + (lane & 3) * 2;
                float c0 = acc[im][jn][0], c1 = acc[im][jn][1];
                float c2 = acc[im][jn][2], c3 = acc[im][jn][3];
                s0 += c0 * c0 + c1 * c1;
                s1 += c2 * c2 + c3 * c3;
                *(__nv_bfloat162*)(C + (size_t)m * KK + n) =
                    __halves2bfloat162(__float2bfloat16(c0), __float2bfloat16(c1));
                *(__nv_bfloat162*)(C + (size_t)(m + 8) * KK + n) =
                    __halves2bfloat162(__float2bfloat16(c2), __float2bfloat16(c3));
            }
            s0 += __shfl_xor_sync(0xffffffffu, s0, 1);
            s0 += __shfl_xor_sync(0xffffffffu, s0, 2);
            s1 += __shfl_xor_sync(0xffffffffu, s1, 1);
            s1 += __shfl_xor_sync(0xffffffffu, s1, 2);
            if ((lane & 3) == 0) {
                atomicAdd(&g_ss[m], s0);
                atomicAdd(&g_ss[m + 8], s1);
            }
        }
    } else {
        float ce0[4] = {0, 0, 0, 0}, ce1[4] = {0, 0, 0, 0};
#pragma unroll
        for (int im = 0; im < 4; im++) {
            int m = m0 + wm * 64 + im * 16 + (lane >> 2);
            float i0 = g_invn[m], i1 = g_invn[m + 8];
#pragma unroll
            for (int jn = 0; jn < 4; jn++) {
                int n = n0 + wn * 32 + jn * 8 + (lane & 3) * 2;
                float c0 = acc[im][jn][0] * i0, c1 = acc[im][jn][1] * i0;
                float c2 = acc[im][jn][2] * i1, c3 = acc[im][jn][3] * i1;
                if (mode == 2) {
                    c0 = fexp((c0 - 1.0f) * INV_T);
                    c1 = fexp((c1 - 1.0f) * INV_T);
                    c2 = fexp((c2 - 1.0f) * INV_T);
                    c3 = fexp((c3 - 1.0f) * INV_T);
                    ce0[jn] += c0 + c2;
                    ce1[jn] += c1 + c3;
                }
                *(__nv_bfloat162*)(C + (size_t)m * KK + n) =
                    __halves2bfloat162(__float2bfloat16(c0), __float2bfloat16(c1));
                *(__nv_bfloat162*)(C + (size_t)(m + 8) * KK + n) =
                    __halves2bfloat162(__float2bfloat16(c2), __float2bfloat16(c3));
            }
        }
        if (mode == 2) {
            // reduce column partials over the 8 lane-groups (rows)
#pragma unroll
            for (int jn = 0; jn < 4; jn++) {
#pragma unroll
                for (int o = 4; o < 32; o <<= 1) {
                    ce0[jn] += __shfl_xor_sync(0xffffffffu, ce0[jn], o);
                    ce1[jn] += __shfl_xor_sync(0xffffffffu, ce1[jn], o);
                }
            }
            if (lane < 4) {
#pragma unroll
                for (int jn = 0; jn < 4; jn++) {
                    scp[wm][wn * 32 + jn * 8 + lane * 2 + 0] = ce0[jn];
                    scp[wm][wn * 32 + jn * 8 + lane * 2 + 1] = ce1[jn];
                }
            }
            __syncthreads();
            if (tid < 128)
                atomicAdd(&g_R[n0 + tid], scp[0][tid] + scp[1][tid]);
        }
    }
}

// ---------------- alpha_k = S / (K * R_k), reset R -----------------------------------
__global__ void k_alpha(int first) {
    int t = threadIdx.x;           // 512
    float Rk = g_R[t];
    __shared__ float sm[512];
    float S;
    if (first) {
        sm[t] = Rk;
        __syncthreads();
        for (int o = 256; o > 0; o >>= 1) {
            if (t < o) sm[t] += sm[t + o];
            __syncthreads();
        }
        S = sm[0];
        if (t == 0) g_S = S;
    } else {
        S = g_S;
    }
    g_alpha[t] = S / (512.0f * Rk);
    g_R[t] = 0.0f;
}

// ---------------- fused sinkhorn iteration: beta per row + colsum accumulate ---------
// one read of E per iteration. grid 128 x 256 threads; warp handles 32 rows.
__global__ void k_rcpass() {
    int wid = threadIdx.x >> 5, lane = threadIdx.x & 31;
    __shared__ float sc[8][512];

    float al[16];
    const float* ap = g_alpha + lane * 16;
#pragma unroll
    for (int j = 0; j < 16; j++) al[j] = ap[j];
    float S = g_S;

    float colp[16];
#pragma unroll
    for (int j = 0; j < 16; j++) colp[j] = 0.0f;

    int row0 = blockIdx.x * 256 + wid * 32;
    for (int r = 0; r < 32; r++) {
        int row = row0 + r;
        const uint4* pe = (const uint4*)(g_E + (size_t)row * KK + lane * 16);
        uint4 u0 = pe[0], u1 = pe[1];
        float ev[16];
        {
            __nv_bfloat162* h0 = (__nv_bfloat162*)&u0;
            __nv_bfloat162* h1 = (__nv_bfloat162*)&u1;
#pragma unroll
            for (int k = 0; k < 4; k++) {
                float2 f0 = __bfloat1622float2(h0[k]);
                float2 f1 = __bfloat1622float2(h1[k]);
                ev[k * 2 + 0] = f0.x; ev[k * 2 + 1] = f0.y;
                ev[8 + k * 2 + 0] = f1.x; ev[8 + k * 2 + 1] = f1.y;
            }
        }
        float dot = 0.0f;
#pragma unroll
        for (int j = 0; j < 16; j++) dot = fmaf(ev[j], al[j], dot);
#pragma unroll
        for (int o = 16; o > 0; o >>= 1) dot += __shfl_xor_sync(0xffffffffu, dot, o);
        float beta = S / (32768.0f * dot);
#pragma unroll
        for (int j = 0; j < 16; j++) colp[j] = fmaf(ev[j], beta, colp[j]);
    }
#pragma unroll
    for (int j = 0; j < 16; j++) sc[wid][lane * 16 + j] = colp[j];
    __syncthreads();
    for (int c = threadIdx.x; c < 512; c += 256) {
        float sum = sc[0][c] + sc[1][c] + sc[2][c] + sc[3][c]
                  + sc[4][c] + sc[5][c] + sc[6][c] + sc[7][c];
        atomicAdd(&g_R[c], sum);
    }
}

// ---------------- fused lse + loss (bf16 inputs) ---------------------------------------
// grid 512 x 256 threads; warp handles 8 rows.
__global__ void k_loss() {
    int wid = threadIdx.x >> 5, lane = threadIdx.x & 31;
    __shared__ float sl[8];

    float al[16];
    const float* ap = g_alpha + lane * 16;
#pragma unroll
    for (int j = 0; j < 16; j++) al[j] = ap[j];

    float lacc = 0.0f;
    int row0 = blockIdx.x * 64 + wid * 8;
    for (int r = 0; r < 8; r++) {
        int row = row0 + r;
        const uint4* pe = (const uint4*)(g_E + (size_t)row * KK + lane * 16);
        const uint4* ps = (const uint4*)(g_Ss + (size_t)row * KK + lane * 16);
        uint4 ue0 = pe[0], ue1 = pe[1], us0 = ps[0], us1 = ps[1];
        float ev[16], v[16];
        {
            __nv_bfloat162* he0 = (__nv_bfloat162*)&ue0;
            __nv_bfloat162* he1 = (__nv_bfloat162*)&ue1;
            __nv_bfloat162* hs0 = (__nv_bfloat162*)&us0;
            __nv_bfloat162* hs1 = (__nv_bfloat162*)&us1;
#pragma unroll
            for (int k = 0; k < 4; k++) {
                float2 f0 = __bfloat1622float2(he0[k]);
                float2 f1 = __bfloat1622float2(he1[k]);
                ev[k * 2] = f0.x; ev[k * 2 + 1] = f0.y;
                ev[8 + k * 2] = f1.x; ev[8 + k * 2 + 1] = f1.y;
                float2 g0 = __bfloat1622float2(hs0[k]);
                float2 g1 = __bfloat1622float2(hs1[k]);
                v[k * 2] = g0.x * INV_T; v[k * 2 + 1] = g0.y * INV_T;
                v[8 + k * 2] = g1.x * INV_T; v[8 + k * 2 + 1] = g1.y * INV_T;
            }
        }
        float mx = v[0];
#pragma unroll
        for (int j = 1; j < 16; j++) mx = fmaxf(mx, v[j]);
#pragma unroll
        for (int o = 16; o > 0; o >>= 1)
            mx = fmaxf(mx, __shfl_xor_sync(0xffffffffu, mx, o));
        float se = 0.0f, C = 0.0f, Acc = 0.0f;
#pragma unroll
        for (int j = 0; j < 16; j++) {
            se += fexp(v[j] - mx);
            float q = ev[j] * al[j];
            C += q;
            Acc = fmaf(q, v[j], Acc);
        }
#pragma unroll
        for (int o = 16; o > 0; o >>= 1) {
            se += __shfl_xor_sync(0xffffffffu, se, o);
            C += __shfl_xor_sync(0xffffffffu, C, o);
            Acc += __shfl_xor_sync(0xffffffffu, Acc, o);
        }
        float lse = mx + logf(se);
        lacc += -(Acc - lse * C) / C;
    }
    if (lane == 0) sl[wid] = lacc;
    __syncthreads();
    if (threadIdx.x == 0) {
        float b = sl[0] + sl[1] + sl[2] + sl[3] + sl[4] + sl[5] + sl[6] + sl[7];
        atomicAdd(&g_loss, b);
    }
}

__global__ void k_final(float* __restrict__ out) {
    out[0] = g_loss * (1.0f / 32768.0f);
}

// ---------------- launch ---------------------------------------------------------------
#define GEMM_SMEM (STAGES * STAGE_BYTES)

extern "C" void kernel_launch(void* const* d_in, const int* in_sizes, int n_in,
                              void* d_out, int out_size) {
    const float* s = nullptr;
    const float* t = nullptr;
    const float* W_net = nullptr;
    const float* W_proto = nullptr;
    for (int i = 0; i < n_in; i++) {
        long long sz = in_sizes[i];
        if (sz == (long long)BB * DD) {
            if (!s) s = (const float*)d_in[i];
            else if (!t) t = (const float*)d_in[i];
        } else if (sz == (long long)KK * DD) {
            W_net = (const float*)d_in[i];
        } else if (sz == (long long)KK * KK) {
            W_proto = (const float*)d_in[i];
        }
    }
    float* out = (float*)d_out;

    __nv_bfloat16 *Ss, *E, *X, *Zb, *W, *Cn;
    cudaGetSymbolAddress((void**)&Ss, g_Ss);
    cudaGetSymbolAddress((void**)&E, g_E);
    cudaGetSymbolAddress((void**)&X, g_X);
    cudaGetSymbolAddress((void**)&Zb, g_Zb);
    cudaGetSymbolAddress((void**)&W, g_W);
    cudaGetSymbolAddress((void**)&Cn, g_Cn);

    cudaFuncSetAttribute(k_gemm, cudaFuncAttributeMaxDynamicSharedMemorySize, GEMM_SMEM);

    dim3 gg(KK / 128, BB / 128);   // (4, 256)

    k_init<<<BB / 512, 512>>>();
    k_proto<<<KK, 128>>>(W_proto);
    k_conv<<<512, 256>>>(W_net, W, (KK * DD) / 4);

    // student branch: Zb = s@W^T (bf16, +sumsq); invn; Ss = bf16(invn*(Zb@Cn^T))
    k_conv<<<8192, 256>>>(s, X, (BB * DD) / 4);
    k_gemm<<<gg, 256, GEMM_SMEM>>>(X, W, Zb, DD, 0);
    k_inv<<<BB / 256, 256>>>();
    k_gemm<<<gg, 256, GEMM_SMEM>>>(Zb, Cn, Ss, KK, 1);

    // teacher branch: E = bf16(fexp((invn*(Zb@Cn^T)-1)*10)), colsums into g_R
    k_conv<<<8192, 256>>>(t, X, (BB * DD) / 4);
    k_gemm<<<gg, 256, GEMM_SMEM>>>(X, W, Zb, DD, 0);
    k_inv<<<BB / 256, 256>>>();
    k_gemm<<<gg, 256, GEMM_SMEM>>>(Zb, Cn, E, KK, 2);

    // sinkhorn (factor form, fused row+col passes)
    k_alpha<<<1, 512>>>(1);
    k_rcpass<<<128, 256>>>();
    k_alpha<<<1, 512>>>(0);
    k_rcpass<<<128, 256>>>();
    k_alpha<<<1, 512>>>(0);

    // fused lse + loss
    k_loss<<<512, 256>>>();
    k_final<<<1, 1>>>(out);
}

// round 8
// speedup vs baseline: 4.9346x; 1.0292x over previous
#include <cuda_runtime.h>
#include <cuda_bf16.h>
#include <math.h>
#include <stdint.h>

#define BB 32768
#define DD 1024
#define KK 512
#define INV_T 10.0f

// ---------------- scratch (static device globals) ----------------------------
__device__ __align__(16) __nv_bfloat16 g_Ss[16777216];   // scores_s bf16
__device__ __align__(16) __nv_bfloat16 g_E[16777216];    // E bf16
__device__ __align__(16) __nv_bfloat16 g_Zb[16777216];   // Z bf16 (unnormalized)
__device__ __align__(16) __nv_bfloat16 g_W[524288];      // W_net bf16
__device__ __align__(16) __nv_bfloat16 g_Cn[262144];     // normalized protos bf16
__device__ float g_ss[BB];      // row sumsq of Z
__device__ float g_invn[BB];    // 1/||Z row||
__device__ float g_R[KK];
__device__ float g_alpha[KK];
__device__ float g_S;
__device__ float g_loss;

// ---------------- helpers ------------------------------------------------------
__device__ __forceinline__ uint32_t smem_u32(const void* p) {
    uint32_t a;
    asm("{ .reg .u64 t; cvta.to.shared.u64 t, %1; cvt.u32.u64 %0, t; }"
        : "=r"(a) : "l"(p));
    return a;
}
__device__ __forceinline__ void cp_async16(uint32_t saddr, const void* g) {
    asm volatile("cp.async.cg.shared.global [%0], [%1], 16;"
                 :: "r"(saddr), "l"(g) : "memory");
}
__device__ __forceinline__ void ldsm_x4(uint32_t* r, uint32_t addr) {
    asm volatile("ldmatrix.sync.aligned.m8n8.x4.shared.b16 {%0,%1,%2,%3}, [%4];"
                 : "=r"(r[0]), "=r"(r[1]), "=r"(r[2]), "=r"(r[3]) : "r"(addr));
}
__device__ __forceinline__ void mma16816(float* c, const uint32_t* a,
                                         uint32_t b0, uint32_t b1) {
    asm volatile(
        "mma.sync.aligned.m16n8k16.row.col.f32.bf16.bf16.f32 "
        "{%0,%1,%2,%3}, {%4,%5,%6,%7}, {%8,%9}, {%0,%1,%2,%3};"
        : "+f"(c[0]), "+f"(c[1]), "+f"(c[2]), "+f"(c[3])
        : "r"(a[0]), "r"(a[1]), "r"(a[2]), "r"(a[3]), "r"(b0), "r"(b1));
}
#define SWZ(o) ((o) ^ (((o) >> 3) & 0x70))

// fast e^x on the FMA pipe (exp2-based, degree-6 poly, rel err ~6e-8)
__device__ __forceinline__ float fexp(float x) {
    float y = x * 1.4426950408889634f;
    float t = y + 12582912.0f;
    int e = __float_as_int(t) - 0x4B400000;
    float f = y - (t - 12582912.0f);
    float p = 1.5403530e-4f;
    p = fmaf(p, f, 1.3333558e-3f);
    p = fmaf(p, f, 9.6181291e-3f);
    p = fmaf(p, f, 5.5504109e-2f);
    p = fmaf(p, f, 2.4022651e-1f);
    p = fmaf(p, f, 6.9314718e-1f);
    p = fmaf(p, f, 1.0f);
    return p * __int_as_float((e + 127) << 23);
}

__device__ __forceinline__ __nv_bfloat162 pack2(float a, float b) {
    return __halves2bfloat162(__float2bfloat16(a), __float2bfloat16(b));
}

// ---------------- init ----------------------------------------------------------
__global__ void k_init() {
    int i = blockIdx.x * blockDim.x + threadIdx.x;
    g_ss[i] = 0.0f;
    if (i < KK) g_R[i] = 0.0f;
    if (i == 0) g_loss = 0.0f;
}

// ---------------- Cn = l2norm rows of W_proto -> bf16 ---------------------------
__global__ void k_proto(const float* __restrict__ W) {
    int row = blockIdx.x;
    int t = threadIdx.x;
    float4 v = ((const float4*)(W + (size_t)row * KK))[t];
    float s = v.x * v.x + v.y * v.y + v.z * v.z + v.w * v.w;
    __shared__ float sm[128];
    sm[t] = s;
    __syncthreads();
    for (int o = 64; o > 0; o >>= 1) {
        if (t < o) sm[t] += sm[t + o];
        __syncthreads();
    }
    float inv = rsqrtf(sm[0]);
    __nv_bfloat162* hp = (__nv_bfloat162*)(g_Cn + (size_t)row * KK + t * 4);
    hp[0] = pack2(v.x * inv, v.y * inv);
    hp[1] = pack2(v.z * inv, v.w * inv);
}

// ---------------- f32 -> bf16 (W_net only; tiny) ----------------------------------
__global__ void k_conv(const float* __restrict__ x, __nv_bfloat16* __restrict__ hd,
                       int n4) {
    int i = blockIdx.x * blockDim.x + threadIdx.x;
    int stride = gridDim.x * blockDim.x;
    for (; i < n4; i += stride) {
        float4 v = ((const float4*)x)[i];
        __nv_bfloat162* hp = (__nv_bfloat162*)(hd + (size_t)i * 4);
        hp[0] = pack2(v.x, v.y);
        hp[1] = pack2(v.z, v.w);
    }
}

// ---------------- invn = rsqrt(ss); ss = 0 ----------------------------------------
__global__ void k_inv() {
    int i = blockIdx.x * blockDim.x + threadIdx.x;
    g_invn[i] = rsqrtf(g_ss[i]);
    g_ss[i] = 0.0f;
}

// ================= gemm1 fused-convert: Zb = bf16(A_f32 @ W^T), sumsq ============
// A: f32 [BB, 1024]. B: bf16 [512, 1024]. 128x128 tile, k-tile 64.
// smem: Abf[2] 16KB @0, Bt[2] 16KB @32768, Ast(f32 half-tiles)[2] 16KB @65536.
// Pipelined at half-k-tile (32 cols) granularity. Occupancy 2 (96KB).
#define G1_ABF 0
#define G1_BT 32768
#define G1_AST 65536
#define G1_SMEM 98304
__global__ void __launch_bounds__(256, 2)
k_gemm1f(const float* __restrict__ A, const __nv_bfloat16* __restrict__ B,
         __nv_bfloat16* __restrict__ C) {
    extern __shared__ char smem[];
    const int Kd = DD;          // 1024
    const int NT = Kd >> 6;     // 16 k-tiles
    const int NH = NT * 2;      // 32 halves

    int tid = threadIdx.x, wid = tid >> 5, lane = tid & 31;
    int m0 = blockIdx.y * 128, n0 = blockIdx.x * 128;
    int wm = wid >> 2, wn = wid & 3;

    uint32_t s_base = smem_u32(smem);

    // --- loaders ---
    int lrow = tid >> 3, lseg = tid & 7;
    const float* gA0 = A + (size_t)(m0 + lrow) * Kd + lseg * 4;
    const __nv_bfloat16* gB0 = B + (size_t)(n0 + lrow) * Kd + lseg * 8;

    auto loadA_half = [&](int H) {              // 16KB f32: 128 rows x 32 cols
        uint32_t sa = s_base + G1_AST + (uint32_t)(H & 1) * 16384;
        int kc = H * 32;
#pragma unroll
        for (int p = 0; p < 4; p++) {
            uint32_t so = SWZ((lrow + p * 32) * 128 + lseg * 16);
            cp_async16(sa + so, gA0 + (size_t)p * 32 * Kd + kc);
        }
    };
    auto loadB = [&](int kt) {                  // 16KB bf16: 128 rows x 64 cols
        uint32_t sa = s_base + G1_BT + (uint32_t)(kt & 1) * 16384;
        int kc = kt * 64;
#pragma unroll
        for (int p = 0; p < 4; p++) {
            uint32_t so = SWZ((lrow + p * 32) * 128 + lseg * 16);
            cp_async16(sa + so, gB0 + (size_t)p * 32 * Kd + kc);
        }
    };

    // --- ldmatrix offsets (tile-relative) ---
    uint32_t offA[4], offB[2];
    {
        int rA = (lane & 7) + ((lane >> 3) & 1) * 8;
        int sA = (lane >> 4) * 16;
#pragma unroll
        for (int im = 0; im < 4; im++) {
            int row = wm * 64 + im * 16 + rA;
            offA[im] = (uint32_t)(row * 128) | (uint32_t)(sA ^ ((row & 7) << 4));
        }
        int rB = (lane & 7) + ((lane >> 4) & 1) * 8;
        int sB = ((lane >> 3) & 1) * 16;
#pragma unroll
        for (int j = 0; j < 2; j++) {
            int row = wn * 32 + j * 16 + rB;
            offB[j] = (uint32_t)(row * 128) | (uint32_t)(sB ^ ((row & 7) << 4));
        }
    }

    float acc[4][4][4];
#pragma unroll
    for (int i = 0; i < 4; i++)
#pragma unroll
        for (int j = 0; j < 4; j++)
#pragma unroll
            for (int k = 0; k < 4; k++) acc[i][j][k] = 0.0f;

    // --- prologue: C0={A half0, B0}; C1={A half1} ---
    loadA_half(0);
    loadB(0);
    asm volatile("cp.async.commit_group;" ::: "memory");
    loadA_half(1);
    asm volatile("cp.async.commit_group;" ::: "memory");

    // convert indices (constant per thread)
    int cb0 = tid * 2, cb1 = tid * 2 + 1;
    int crow0 = cb0 >> 2, cg0 = cb0 & 3;
    int crow1 = cb1 >> 2, cg1 = cb1 & 3;

    for (int H = 0; H < NH; H++) {
        int kt = H >> 1, h = H & 1, st = kt & 1;
        asm volatile("cp.async.wait_group 1;" ::: "memory");
        __syncthreads();

        // --- convert staging (f32 half) -> Abf[st] k-cols [32h, 32h+32) ---
        {
            uint32_t ast = s_base + G1_AST + (uint32_t)(H & 1) * 16384;
            uint32_t abf = s_base + G1_ABF + (uint32_t)st * 16384;
#pragma unroll
            for (int q = 0; q < 2; q++) {
                int row = q ? crow1 : crow0;
                int g = q ? cg1 : cg0;
                float4 f0, f1;
                asm volatile("ld.shared.v4.f32 {%0,%1,%2,%3}, [%4];"
                             : "=f"(f0.x), "=f"(f0.y), "=f"(f0.z), "=f"(f0.w)
                             : "r"(ast + SWZ(row * 128 + g * 32)));
                asm volatile("ld.shared.v4.f32 {%0,%1,%2,%3}, [%4];"
                             : "=f"(f1.x), "=f"(f1.y), "=f"(f1.z), "=f"(f1.w)
                             : "r"(ast + SWZ(row * 128 + g * 32 + 16)));
                __nv_bfloat162 p0 = pack2(f0.x, f0.y), p1 = pack2(f0.z, f0.w);
                __nv_bfloat162 p2 = pack2(f1.x, f1.y), p3 = pack2(f1.z, f1.w);
                uint32_t u0 = *(uint32_t*)&p0, u1 = *(uint32_t*)&p1;
                uint32_t u2 = *(uint32_t*)&p2, u3 = *(uint32_t*)&p3;
                asm volatile("st.shared.v4.b32 [%0], {%1,%2,%3,%4};"
                             :: "r"(abf + SWZ(row * 128 + h * 64 + g * 16)),
                                "r"(u0), "r"(u1), "r"(u2), "r"(u3) : "memory");
            }
        }
        __syncthreads();

        // --- issue C_{H+2}: A half H+2 (+ B_{kt+1} when h==0) ---
        if (H + 2 < NH) loadA_half(H + 2);
        if (h == 0 && kt + 1 < NT) loadB(kt + 1);
        asm volatile("cp.async.commit_group;" ::: "memory");

        // --- compute k-steps {2h, 2h+1} ---
        uint32_t sbA = s_base + G1_ABF + (uint32_t)st * 16384;
        uint32_t sbB = s_base + G1_BT + (uint32_t)st * 16384;
#pragma unroll
        for (int kss = 0; kss < 2; kss++) {
            uint32_t kx = (uint32_t)((2 * h + kss) << 5);
            uint32_t a[4][4], b[2][4];
#pragma unroll
            for (int im = 0; im < 4; im++) ldsm_x4(a[im], sbA + (offA[im] ^ kx));
#pragma unroll
            for (int j = 0; j < 2; j++) ldsm_x4(b[j], sbB + (offB[j] ^ kx));
#pragma unroll
            for (int im = 0; im < 4; im++)
#pragma unroll
                for (int j = 0; j < 2; j++) {
                    mma16816(acc[im][j * 2 + 0], a[im], b[j][0], b[j][1]);
                    mma16816(acc[im][j * 2 + 1], a[im], b[j][2], b[j][3]);
                }
        }
    }

    // ---- epilogue: bf16 out + row sumsq ----
#pragma unroll
    for (int im = 0; im < 4; im++) {
        int m = m0 + wm * 64 + im * 16 + (lane >> 2);
        float s0 = 0.0f, s1 = 0.0f;
#pragma unroll
        for (int jn = 0; jn < 4; jn++) {
            int n = n0 + wn * 32 + jn * 8 + (lane & 3) * 2;
            float c0 = acc[im][jn][0], c1 = acc[im][jn][1];
            float c2 = acc[im][jn][2], c3 = acc[im][jn][3];
            s0 += c0 * c0 + c1 * c1;
            s1 += c2 * c2 + c3 * c3;
            *(__nv_bfloat162*)(C + (size_t)m * KK + n) = pack2(c0, c1);
            *(__nv_bfloat162*)(C + (size_t)(m + 8) * KK + n) = pack2(c2, c3);
        }
        s0 += __shfl_xor_sync(0xffffffffu, s0, 1);
        s0 += __shfl_xor_sync(0xffffffffu, s0, 2);
        s1 += __shfl_xor_sync(0xffffffffu, s1, 1);
        s1 += __shfl_xor_sync(0xffffffffu, s1, 2);
        if ((lane & 3) == 0) {
            atomicAdd(&g_ss[m], s0);
            atomicAdd(&g_ss[m + 8], s1);
        }
    }
}

// ================= gemm2 (bf16 A): scores / E ====================================
// mode 1: out = bf16(acc * invn[m])                              (student)
// mode 2: out = bf16(fexp((acc*invn[m]-1)*10)), colsums -> g_R   (teacher)
#define STAGES 3
#define STAGE_BYTES 32768
__global__ void __launch_bounds__(256, 2)
k_gemm(const __nv_bfloat16* __restrict__ A, const __nv_bfloat16* __restrict__ B,
       __nv_bfloat16* __restrict__ C, int Kd, int mode) {
    extern __shared__ char smem[];
    __shared__ float scp[2][128];

    int tid = threadIdx.x, wid = tid >> 5, lane = tid & 31;
    int m0 = blockIdx.y * 128, n0 = blockIdx.x * 128;
    int wm = wid >> 2, wn = wid & 3;

    uint32_t s_base = smem_u32(smem);
    int NT = Kd >> 6;

    int lrow = tid >> 3, lseg = tid & 7;
    const __nv_bfloat16* gA0 = A + (size_t)(m0 + lrow) * Kd + lseg * 8;
    const __nv_bfloat16* gB0 = B + (size_t)(n0 + lrow) * Kd + lseg * 8;
    auto load = [&](int kt, int st) {
        int kc = kt * 64;
        uint32_t sa = s_base + st * STAGE_BYTES;
#pragma unroll
        for (int p = 0; p < 4; p++) {
            uint32_t so = SWZ((lrow + p * 32) * 128 + lseg * 16);
            cp_async16(sa + so, gA0 + (size_t)p * 32 * Kd + kc);
            cp_async16(sa + 16384 + so, gB0 + (size_t)p * 32 * Kd + kc);
        }
        asm volatile("cp.async.commit_group;" ::: "memory");
    };

    uint32_t offA[4], offB[2];
    {
        int rA = (lane & 7) + ((lane >> 3) & 1) * 8;
        int sA = (lane >> 4) * 16;
#pragma unroll
        for (int im = 0; im < 4; im++) {
            int row = wm * 64 + im * 16 + rA;
            offA[im] = (uint32_t)(row * 128) | (uint32_t)(sA ^ ((row & 7) << 4));
        }
        int rB = (lane & 7) + ((lane >> 4) & 1) * 8;
        int sB = ((lane >> 3) & 1) * 16;
#pragma unroll
        for (int j = 0; j < 2; j++) {
            int row = wn * 32 + j * 16 + rB;
            offB[j] = 16384u + ((uint32_t)(row * 128) |
                                (uint32_t)(sB ^ ((row & 7) << 4)));
        }
    }

    float acc[4][4][4];
#pragma unroll
    for (int i = 0; i < 4; i++)
#pragma unroll
        for (int j = 0; j < 4; j++)
#pragma unroll
            for (int k = 0; k < 4; k++) acc[i][j][k] = 0.0f;

    load(0, 0);
    load(1, 1);

    for (int kt = 0; kt < NT; kt++) {
        asm volatile("cp.async.wait_group 1;" ::: "memory");
        __syncthreads();
        uint32_t sb = s_base + (uint32_t)(kt % 3) * STAGE_BYTES;
#pragma unroll
        for (int ks = 0; ks < 4; ks++) {
            uint32_t kx = (uint32_t)(ks << 5);
            uint32_t a[4][4], b[2][4];
#pragma unroll
            for (int im = 0; im < 4; im++) ldsm_x4(a[im], sb + (offA[im] ^ kx));
#pragma unroll
            for (int j = 0; j < 2; j++) ldsm_x4(b[j], sb + (offB[j] ^ kx));
#pragma unroll
            for (int im = 0; im < 4; im++)
#pragma unroll
                for (int j = 0; j < 2; j++) {
                    mma16816(acc[im][j * 2 + 0], a[im], b[j][0], b[j][1]);
                    mma16816(acc[im][j * 2 + 1], a[im], b[j][2], b[j][3]);
                }
        }
        if (kt + 2 < NT) load(kt + 2, (kt + 2) % 3);
        else asm volatile("cp.async.commit_group;" ::: "memory");
    }

    float ce0[4] = {0, 0, 0, 0}, ce1[4] = {0, 0, 0, 0};
#pragma unroll
    for (int im = 0; im < 4; im++) {
        int m = m0 + wm * 64 + im * 16 + (lane >> 2);
        float i0 = g_invn[m], i1 = g_invn[m + 8];
#pragma unroll
        for (int jn = 0; jn < 4; jn++) {
            int n = n0 + wn * 32 + jn * 8 + (lane & 3) * 2;
            float c0 = acc[im][jn][0] * i0, c1 = acc[im][jn][1] * i0;
            float c2 = acc[im][jn][2] * i1, c3 = acc[im][jn][3] * i1;
            if (mode == 2) {
                c0 = fexp((c0 - 1.0f) * INV_T);
                c1 = fexp((c1 - 1.0f) * INV_T);
                c2 = fexp((c2 - 1.0f) * INV_T);
                c3 = fexp((c3 - 1.0f) * INV_T);
                ce0[jn] += c0 + c2;
                ce1[jn] += c1 + c3;
            }
            *(__nv_bfloat162*)(C + (size_t)m * KK + n) = pack2(c0, c1);
            *(__nv_bfloat162*)(C + (size_t)(m + 8) * KK + n) = pack2(c2, c3);
        }
    }
    if (mode == 2) {
#pragma unroll
        for (int jn = 0; jn < 4; jn++) {
#pragma unroll
            for (int o = 4; o < 32; o <<= 1) {
                ce0[jn] += __shfl_xor_sync(0xffffffffu, ce0[jn], o);
                ce1[jn] += __shfl_xor_sync(0xffffffffu, ce1[jn], o);
            }
        }
        if (lane < 4) {
#pragma unroll
            for (int jn = 0; jn < 4; jn++) {
                scp[wm][wn * 32 + jn * 8 + lane * 2 + 0] = ce0[jn];
                scp[wm][wn * 32 + jn * 8 + lane * 2 + 1] = ce1[jn];
            }
        }
        __syncthreads();
        if (tid < 128)
            atomicAdd(&g_R[n0 + tid], scp[0][tid] + scp[1][tid]);
    }
}

// ---------------- alpha_k = S / (K * R_k), reset R -----------------------------------
__global__ void k_alpha(int first) {
    int t = threadIdx.x;           // 512
    float Rk = g_R[t];
    __shared__ float sm[512];
    float S;
    if (first) {
        sm[t] = Rk;
        __syncthreads();
        for (int o = 256; o > 0; o >>= 1) {
            if (t < o) sm[t] += sm[t + o];
            __syncthreads();
        }
        S = sm[0];
        if (t == 0) g_S = S;
    } else {
        S = g_S;
    }
    g_alpha[t] = S / (512.0f * Rk);
    g_R[t] = 0.0f;
}

// ---------------- fused sinkhorn iteration ------------------------------------------
__global__ void k_rcpass() {
    int wid = threadIdx.x >> 5, lane = threadIdx.x & 31;
    __shared__ float sc[8][512];

    float al[16];
    const float* ap = g_alpha + lane * 16;
#pragma unroll
    for (int j = 0; j < 16; j++) al[j] = ap[j];
    float S = g_S;

    float colp[16];
#pragma unroll
    for (int j = 0; j < 16; j++) colp[j] = 0.0f;

    int row0 = blockIdx.x * 256 + wid * 32;
    for (int r = 0; r < 32; r++) {
        int row = row0 + r;
        const uint4* pe = (const uint4*)(g_E + (size_t)row * KK + lane * 16);
        uint4 u0 = pe[0], u1 = pe[1];
        float ev[16];
        {
            __nv_bfloat162* h0 = (__nv_bfloat162*)&u0;
            __nv_bfloat162* h1 = (__nv_bfloat162*)&u1;
#pragma unroll
            for (int k = 0; k < 4; k++) {
                float2 f0 = __bfloat1622float2(h0[k]);
                float2 f1 = __bfloat1622float2(h1[k]);
                ev[k * 2 + 0] = f0.x; ev[k * 2 + 1] = f0.y;
                ev[8 + k * 2 + 0] = f1.x; ev[8 + k * 2 + 1] = f1.y;
            }
        }
        float dot = 0.0f;
#pragma unroll
        for (int j = 0; j < 16; j++) dot = fmaf(ev[j], al[j], dot);
#pragma unroll
        for (int o = 16; o > 0; o >>= 1) dot += __shfl_xor_sync(0xffffffffu, dot, o);
        float beta = S / (32768.0f * dot);
#pragma unroll
        for (int j = 0; j < 16; j++) colp[j] = fmaf(ev[j], beta, colp[j]);
    }
#pragma unroll
    for (int j = 0; j < 16; j++) sc[wid][lane * 16 + j] = colp[j];
    __syncthreads();
    for (int c = threadIdx.x; c < 512; c += 256) {
        float sum = sc[0][c] + sc[1][c] + sc[2][c] + sc[3][c]
                  + sc[4][c] + sc[5][c] + sc[6][c] + sc[7][c];
        atomicAdd(&g_R[c], sum);
    }
}

// ---------------- fused lse + loss ----------------------------------------------------
__global__ void k_loss() {
    int wid = threadIdx.x >> 5, lane = threadIdx.x & 31;
    __shared__ float sl[8];

    float al[16];
    const float* ap = g_alpha + lane * 16;
#pragma unroll
    for (int j = 0; j < 16; j++) al[j] = ap[j];

    float lacc = 0.0f;
    int row0 = blockIdx.x * 64 + wid * 8;
    for (int r = 0; r < 8; r++) {
        int row = row0 + r;
        const uint4* pe = (const uint4*)(g_E + (size_t)row * KK + lane * 16);
        const uint4* ps = (const uint4*)(g_Ss + (size_t)row * KK + lane * 16);
        uint4 ue0 = pe[0], ue1 = pe[1], us0 = ps[0], us1 = ps[1];
        float ev[16], v[16];
        {
            __nv_bfloat162* he0 = (__nv_bfloat162*)&ue0;
            __nv_bfloat162* he1 = (__nv_bfloat162*)&ue1;
            __nv_bfloat162* hs0 = (__nv_bfloat162*)&us0;
            __nv_bfloat162* hs1 = (__nv_bfloat162*)&us1;
#pragma unroll
            for (int k = 0; k < 4; k++) {
                float2 f0 = __bfloat1622float2(he0[k]);
                float2 f1 = __bfloat1622float2(he1[k]);
                ev[k * 2] = f0.x; ev[k * 2 + 1] = f0.y;
                ev[8 + k * 2] = f1.x; ev[8 + k * 2 + 1] = f1.y;
                float2 g0 = __bfloat1622float2(hs0[k]);
                float2 g1 = __bfloat1622float2(hs1[k]);
                v[k * 2] = g0.x * INV_T; v[k * 2 + 1] = g0.y * INV_T;
                v[8 + k * 2] = g1.x * INV_T; v[8 + k * 2 + 1] = g1.y * INV_T;
            }
        }
        float mx = v[0];
#pragma unroll
        for (int j = 1; j < 16; j++) mx = fmaxf(mx, v[j]);
#pragma unroll
        for (int o = 16; o > 0; o >>= 1)
            mx = fmaxf(mx, __shfl_xor_sync(0xffffffffu, mx, o));
        float se = 0.0f, C = 0.0f, Acc = 0.0f;
#pragma unroll
        for (int j = 0; j < 16; j++) {
            se += fexp(v[j] - mx);
            float q = ev[j] * al[j];
            C += q;
            Acc = fmaf(q, v[j], Acc);
        }
#pragma unroll
        for (int o = 16; o > 0; o >>= 1) {
            se += __shfl_xor_sync(0xffffffffu, se, o);
            C += __shfl_xor_sync(0xffffffffu, C, o);
            Acc += __shfl_xor_sync(0xffffffffu, Acc, o);
        }
        float lse = mx + logf(se);
        lacc += -(Acc - lse * C) / C;
    }
    if (lane == 0) sl[wid] = lacc;
    __syncthreads();
    if (threadIdx.x == 0) {
        float b = sl[0] + sl[1] + sl[2] + sl[3] + sl[4] + sl[5] + sl[6] + sl[7];
        atomicAdd(&g_loss, b);
    }
}

__global__ void k_final(float* __restrict__ out) {
    out[0] = g_loss * (1.0f / 32768.0f);
}

// ---------------- launch ---------------------------------------------------------------
#define GEMM_SMEM (STAGES * STAGE_BYTES)

extern "C" void kernel_launch(void* const* d_in, const int* in_sizes, int n_in,
                              void* d_out, int out_size) {
    const float* s = nullptr;
    const float* t = nullptr;
    const float* W_net = nullptr;
    const float* W_proto = nullptr;
    for (int i = 0; i < n_in; i++) {
        long long sz = in_sizes[i];
        if (sz == (long long)BB * DD) {
            if (!s) s = (const float*)d_in[i];
            else if (!t) t = (const float*)d_in[i];
        } else if (sz == (long long)KK * DD) {
            W_net = (const float*)d_in[i];
        } else if (sz == (long long)KK * KK) {
            W_proto = (const float*)d_in[i];
        }
    }
    float* out = (float*)d_out;

    __nv_bfloat16 *Ss, *E, *Zb, *W, *Cn;
    cudaGetSymbolAddress((void**)&Ss, g_Ss);
    cudaGetSymbolAddress((void**)&E, g_E);
    cudaGetSymbolAddress((void**)&Zb, g_Zb);
    cudaGetSymbolAddress((void**)&W, g_W);
    cudaGetSymbolAddress((void**)&Cn, g_Cn);

    cudaFuncSetAttribute(k_gemm1f, cudaFuncAttributeMaxDynamicSharedMemorySize, G1_SMEM);
    cudaFuncSetAttribute(k_gemm, cudaFuncAttributeMaxDynamicSharedMemorySize, GEMM_SMEM);

    dim3 gg(KK / 128, BB / 128);   // (4, 256)

    k_init<<<BB / 512, 512>>>();
    k_proto<<<KK, 128>>>(W_proto);
    k_conv<<<512, 256>>>(W_net, W, (KK * DD) / 4);

    // student branch: Zb = bf16(s@W^T) + sumsq (fused f32 conv); Ss = bf16(invn*(Zb@Cn^T))
    k_gemm1f<<<gg, 256, G1_SMEM>>>(s, W, Zb);
    k_inv<<<BB / 256, 256>>>();
    k_gemm<<<gg, 256, GEMM_SMEM>>>(Zb, Cn, Ss, KK, 1);

    // teacher branch: E = bf16(fexp((invn*(Zb@Cn^T)-1)*10)), colsums into g_R
    k_gemm1f<<<gg, 256, G1_SMEM>>>(t, W, Zb);
    k_inv<<<BB / 256, 256>>>();
    k_gemm<<<gg, 256, GEMM_SMEM>>>(Zb, Cn, E, KK, 2);

    // sinkhorn (factor form, fused row+col passes)
    k_alpha<<<1, 512>>>(1);
    k_rcpass<<<128, 256>>>();
    k_alpha<<<1, 512>>>(0);
    k_rcpass<<<128, 256>>>();
    k_alpha<<<1, 512>>>(0);

    // fused lse + loss
    k_loss<<<512, 256>>>();
    k_final<<<1, 1>>>(out);
}